// round 11
// baseline (speedup 1.0000x reference)
#include <cuda_runtime.h>
#include <cuda_bf16.h>
#include <math.h>
#include <stdint.h>

// Problem constants
#define BS 512
#define NE 256
#define NQ 64
#define IN_DIM 512
#define EMBED_DIM 512
#define OUT_DIM 512
#define N_HEADS 8
#define HEAD_DIM 64
#define QKV_DIM (3 * EMBED_DIM)

// Arch-feature gate: tcgen05 / f32x2 / multicast only exist in arch-specific passes.
#if defined(__CUDA_ARCH__) && (defined(__CUDA_ARCH_FEAT_SM103_ALL) || defined(__CUDA_ARCH_FEAT_SM100_ALL) || defined(__CUDA_ARCH_FEAT_SM101_ALL))
#define HAS_TCGEN05 1
#else
#define HAS_TCGEN05 0
#endif

// ---------------------------------------------------------------------------
// Scratch (device globals). GEMM operands live in TILE-CONTIGUOUS,
// PRE-SWIZZLED (SW128) layout: [M/128 panels][8 K-chunks][16384 bytes].
// ---------------------------------------------------------------------------
__device__ float g_Q[(size_t)BS * NQ * EMBED_DIM];
__device__ float g_KV[(size_t)BS * NE * (2 * EMBED_DIM)];
__device__ __align__(1024) __nv_bfloat16 g_ent_hi[(size_t)BS * NE * IN_DIM];
__device__ __align__(1024) __nv_bfloat16 g_ent_lo[(size_t)BS * NE * IN_DIM];
__device__ __align__(1024) __nv_bfloat16 g_q_hi[(size_t)BS * NQ * IN_DIM];
__device__ __align__(1024) __nv_bfloat16 g_q_lo[(size_t)BS * NQ * IN_DIM];
__device__ __align__(1024) __nv_bfloat16 g_attn_hi[(size_t)BS * NQ * EMBED_DIM];
__device__ __align__(1024) __nv_bfloat16 g_attn_lo[(size_t)BS * NQ * EMBED_DIM];
__device__ __align__(1024) __nv_bfloat16 g_WinT_hi[(size_t)QKV_DIM * IN_DIM];
__device__ __align__(1024) __nv_bfloat16 g_WinT_lo[(size_t)QKV_DIM * IN_DIM];
__device__ __align__(1024) __nv_bfloat16 g_WoutT_hi[(size_t)OUT_DIM * EMBED_DIM];
__device__ __align__(1024) __nv_bfloat16 g_WoutT_lo[(size_t)OUT_DIM * EMBED_DIM];

// ---------------------------------------------------------------------------
// Common helpers
// ---------------------------------------------------------------------------
__device__ __forceinline__ uint32_t smem_u32(const void* p) {
    uint32_t a;
    asm("{ .reg .u64 t; cvta.to.shared.u64 t, %1; cvt.u32.u64 %0, t; }" : "=r"(a) : "l"(p));
    return a;
}
__device__ __forceinline__ void cp16(uint32_t s, const void* g) {
    asm volatile("cp.async.cg.shared.global [%0], [%1], 16;" :: "r"(s), "l"(g) : "memory");
}
__device__ __forceinline__ void ldsm4(uint32_t* r, uint32_t addr) {
    asm volatile("ldmatrix.sync.aligned.m8n8.x4.shared.b16 {%0,%1,%2,%3}, [%4];"
                 : "=r"(r[0]), "=r"(r[1]), "=r"(r[2]), "=r"(r[3]) : "r"(addr));
}
__device__ __forceinline__ void mma_bf16(float* d, const uint32_t* a, const uint32_t* b) {
    asm volatile("mma.sync.aligned.m16n8k16.row.col.f32.bf16.bf16.f32 "
                 "{%0,%1,%2,%3}, {%4,%5,%6,%7}, {%8,%9}, {%0,%1,%2,%3};"
                 : "+f"(d[0]), "+f"(d[1]), "+f"(d[2]), "+f"(d[3])
                 : "r"(a[0]), "r"(a[1]), "r"(a[2]), "r"(a[3]), "r"(b[0]), "r"(b[1]));
}

// fp32[8] -> bf16 hi/lo packed 16B units
__device__ __forceinline__ void pack8(const float* src, uint4& hv, uint4& lv) {
    __nv_bfloat16 hb[8], lb[8];
#pragma unroll
    for (int j = 0; j < 8; ++j) {
        hb[j] = __float2bfloat16(src[j]);
        lb[j] = __float2bfloat16(src[j] - __bfloat162float(hb[j]));
    }
    uint32_t* hp = (uint32_t*)&hv;
    uint32_t* lp = (uint32_t*)&lv;
#pragma unroll
    for (int j = 0; j < 4; ++j) {
        __nv_bfloat162 h2; h2.x = hb[2 * j]; h2.y = hb[2 * j + 1];
        __nv_bfloat162 l2; l2.x = lb[2 * j]; l2.y = lb[2 * j + 1];
        hp[j] = *(uint32_t*)&h2;
        lp[j] = *(uint32_t*)&l2;
    }
}

// fp32[4] -> bf16 hi/lo packed 8B units
__device__ __forceinline__ void pack4(const float* src, uint2& hv, uint2& lv) {
    __nv_bfloat16 hb[4], lb[4];
#pragma unroll
    for (int j = 0; j < 4; ++j) {
        hb[j] = __float2bfloat16(src[j]);
        lb[j] = __float2bfloat16(src[j] - __bfloat162float(hb[j]));
    }
    uint32_t* hp = (uint32_t*)&hv;
    uint32_t* lp = (uint32_t*)&lv;
#pragma unroll
    for (int j = 0; j < 2; ++j) {
        __nv_bfloat162 h2; h2.x = hb[2 * j]; h2.y = hb[2 * j + 1];
        __nv_bfloat162 l2; l2.x = lb[2 * j]; l2.y = lb[2 * j + 1];
        hp[j] = *(uint32_t*)&h2;
        lp[j] = *(uint32_t*)&l2;
    }
}

// byte offset of (m, k) in tiled+swizzled layout (k multiple of 8)
__device__ __forceinline__ size_t tiled_off(int m, int k) {
    const int panel = m >> 7, r = m & 127, ch = k >> 6;
    uint32_t off = (uint32_t)(r << 7) + ((k & 63) << 1);
    off = off ^ ((off >> 3) & 0x70);
    return ((size_t)(panel * 8 + ch) << 14) + off;
}

#define CLUSTER_SYNC() do { \
    asm volatile("barrier.cluster.arrive.aligned;" ::: "memory"); \
    asm volatile("barrier.cluster.wait.aligned;" ::: "memory"); \
} while (0)

#if HAS_TCGEN05
// ---------------------------------------------------------------------------
// tcgen05 + bulk-async + multicast + f32x2 helpers (arch-specific pass only)
// ---------------------------------------------------------------------------
__device__ __forceinline__ uint32_t elect_one_pred() {
    uint32_t p;
    asm volatile("{\n\t.reg .pred p;\n\telect.sync _|p, 0xFFFFFFFF;\n\tselp.b32 %0, 1, 0, p;\n\t}" : "=r"(p));
    return p;
}
__device__ __forceinline__ uint32_t cluster_rank() {
    uint32_t r;
    asm("mov.u32 %0, %%cluster_ctarank;" : "=r"(r));
    return r;
}
#define TCGEN05_ALLOC(sa, n) \
    asm volatile("tcgen05.alloc.cta_group::1.sync.aligned.shared::cta.b32 [%0], %1;" :: "r"((uint32_t)(sa)), "r"((uint32_t)(n)) : "memory")
#define TCGEN05_DEALLOC(t, n) \
    asm volatile("tcgen05.dealloc.cta_group::1.sync.aligned.b32 %0, %1;" :: "r"(t), "r"((uint32_t)(n)))
#define TCGEN05_RELINQ() \
    asm volatile("tcgen05.relinquish_alloc_permit.cta_group::1.sync.aligned;")
#define TCGEN05_COMMIT_MC(mb, mask) \
    asm volatile("tcgen05.commit.cta_group::1.mbarrier::arrive::one.shared::cluster.multicast::cluster.b64 [%0], %1;" \
                 :: "r"((uint32_t)(mb)), "h"((uint16_t)(mask)) : "memory")
#define TCGEN05_FENCE_AFTER() asm volatile("tcgen05.fence::after_thread_sync;" ::: "memory")
#define TCGEN05_FENCE_BEFORE() asm volatile("tcgen05.fence::before_thread_sync;" ::: "memory")
#define TCGEN05_WAIT_LD() asm volatile("tcgen05.wait::ld.sync.aligned;" ::: "memory")
#define MBARRIER_INIT(mb, cnt) \
    asm volatile("mbarrier.init.shared.b64 [%0], %1;" :: "r"((uint32_t)(mb)), "r"((uint32_t)(cnt)) : "memory")
#define MBARRIER_INVAL(mb) \
    asm volatile("mbarrier.inval.shared.b64 [%0];" :: "r"((uint32_t)(mb)) : "memory")
#define MBARRIER_EXPECT_TX(mb, tx) \
    asm volatile("mbarrier.arrive.expect_tx.shared.b64 _, [%0], %1;" :: "r"((uint32_t)(mb)), "r"((uint32_t)(tx)) : "memory")
#define MBARRIER_WAIT_PARITY(mb, par) do {                                           \
    uint32_t _mb = (uint32_t)(mb); uint32_t _p = (uint32_t)(par); uint32_t _d;       \
    asm volatile("{\n\t.reg .pred p;\n\t"                                            \
        "mbarrier.try_wait.parity.acquire.cta.shared::cta.b64 p, [%1], %2;\n\t"      \
        "selp.b32 %0, 1, 0, p;\n\t}" : "=r"(_d) : "r"(_mb), "r"(_p) : "memory");     \
    if (!_d) {                                                                       \
        asm volatile("{\n\t.reg .pred P1;\n\t"                                       \
            "WL_%=:\n\t"                                                             \
            "mbarrier.try_wait.parity.acquire.cta.shared::cta.b64 P1, [%0], %1, 0x989680;\n\t" \
            "@P1 bra.uni WD_%=;\n\t"                                                 \
            "bra.uni WL_%=;\n\t"                                                     \
            "WD_%=:\n\t}" :: "r"(_mb), "r"(_p) : "memory");                          \
    }                                                                                \
} while (0)

__device__ __forceinline__ void cp_bulk(uint32_t dst, const void* src, uint32_t bytes, uint32_t mb) {
    asm volatile("cp.async.bulk.shared::cta.global.mbarrier::complete_tx::bytes [%0], [%1], %2, [%3];"
                 :: "r"(dst), "l"(src), "r"(bytes), "r"(mb) : "memory");
}
// multicast bulk: delivers data + complete_tx to same smem offsets in all CTAs in mask
__device__ __forceinline__ void cp_bulk_mc(uint32_t dst, const void* src, uint32_t bytes,
                                           uint32_t mb, uint16_t mask) {
    asm volatile("cp.async.bulk.shared::cluster.global.mbarrier::complete_tx::bytes.multicast::cluster "
                 "[%0], [%1], %2, [%3], %4;"
                 :: "r"(dst), "l"(src), "r"(bytes), "r"(mb), "h"(mask) : "memory");
}

#define TCGEN05_LD_32X32B_X32(r, ta) \
    asm volatile( \
        "tcgen05.ld.sync.aligned.32x32b.x32.b32 " \
        "{%0, %1, %2, %3, %4, %5, %6, %7, " \
        " %8, %9, %10, %11, %12, %13, %14, %15, " \
        " %16, %17, %18, %19, %20, %21, %22, %23, " \
        " %24, %25, %26, %27, %28, %29, %30, %31}, [%32];" \
        : "=r"((r)[0]),  "=r"((r)[1]),  "=r"((r)[2]),  "=r"((r)[3]), \
          "=r"((r)[4]),  "=r"((r)[5]),  "=r"((r)[6]),  "=r"((r)[7]), \
          "=r"((r)[8]),  "=r"((r)[9]),  "=r"((r)[10]), "=r"((r)[11]), \
          "=r"((r)[12]), "=r"((r)[13]), "=r"((r)[14]), "=r"((r)[15]), \
          "=r"((r)[16]), "=r"((r)[17]), "=r"((r)[18]), "=r"((r)[19]), \
          "=r"((r)[20]), "=r"((r)[21]), "=r"((r)[22]), "=r"((r)[23]), \
          "=r"((r)[24]), "=r"((r)[25]), "=r"((r)[26]), "=r"((r)[27]), \
          "=r"((r)[28]), "=r"((r)[29]), "=r"((r)[30]), "=r"((r)[31]) \
        : "r"(ta))

static constexpr uint64_t SMEM_DESC_BASE_SW128 =
    (uint64_t(2) << 61) | (uint64_t(1) << 46) | (uint64_t(64) << 32) | (uint64_t(1) << 16);
#define MAKE_SMEM_DESC(ba) (SMEM_DESC_BASE_SW128 | ((uint64_t)((ba) >> 4) & 0x3FFF))

// Proven operand binding: %3 = idesc, %4 = enable, %5 = zero reg.
__device__ __forceinline__ void mma_bf16_ss(uint32_t d, uint64_t da, uint64_t db,
                                            uint32_t idesc, bool en) {
    uint32_t e = en ? 1u : 0u;
    asm volatile(
        "{\n\t.reg .pred p;\n\t"
        "setp.ne.u32 p, %4, 0;\n\t"
        "tcgen05.mma.cta_group::1.kind::f16 [%0], %1, %2, %3, {%5, %5, %5, %5}, p;\n\t"
        "}"
        :: "r"(d), "l"(da), "l"(db), "r"(idesc), "r"(e), "r"(0u)
        : "memory");
}
// idesc: f32 accum, bf16 a, bf16 b, N=128, M=128
static constexpr uint32_t MMA_IDESC =
    (1u << 4) | (1u << 7) | (1u << 10) | ((128u / 8) << 17) | ((128u / 16) << 24);

// packed fp32x2 FMA (FFMA2)
__device__ __forceinline__ void fma2(unsigned long long& d,
                                     unsigned long long a, unsigned long long b) {
    asm("fma.rn.f32x2 %0, %1, %2, %0;" : "+l"(d) : "l"(a), "l"(b));
}
__device__ __forceinline__ unsigned long long dup2(float w) {
    unsigned long long r;
    asm("mov.b64 %0, {%1, %1};" : "=l"(r) : "r"(__float_as_uint(w)));
    return r;
}
__device__ __forceinline__ float lo32(unsigned long long a) {
    return __uint_as_float((uint32_t)a);
}
__device__ __forceinline__ float hi32(unsigned long long a) {
    return __uint_as_float((uint32_t)(a >> 32));
}
#endif // HAS_TCGEN05

#define GK 512
#define NCHUNKS 8
#define TILE_BYTES 16384

// ---------------------------------------------------------------------------
// bf16x3 GEMM: 128x128 tile, 3-stage pipeline (Round-9 measured-best),
// NOW with cluster-2 A-tile multicast: paired n-tiles (same m-panel) share A.
// ---------------------------------------------------------------------------
#define STAGE_BYTES (4 * TILE_BYTES)
#define NSTAGES 3
#define GEMM_DYN_SMEM (NSTAGES * STAGE_BYTES + 1024)

template <bool EPI>
__global__ void __launch_bounds__(256, 1) __cluster_dims__(2, 1, 1)
gemm_bf16x3(const __nv_bfloat16* __restrict__ Ahi, const __nv_bfloat16* __restrict__ Alo,
            const __nv_bfloat16* __restrict__ Bhi, const __nv_bfloat16* __restrict__ Blo,
            float* __restrict__ C, int ldc,
            const float* __restrict__ bias, const int* __restrict__ post_mask)
{
    extern __shared__ char dyn_smem[];
    const int tid = threadIdx.x;
    const int wid = tid >> 5;
    const int lane = tid & 31;
    const int m0 = blockIdx.y << 7;
    const int n0 = blockIdx.x << 7;
    const int pm = blockIdx.y;
    const int pn = blockIdx.x;

    const uint32_t sbase = (smem_u32(dyn_smem) + 1023u) & ~1023u;

#if HAS_TCGEN05
    __shared__ uint32_t s_tmem_ptr[2];
    __shared__ __align__(8) uint64_t s_full[NSTAGES];
    __shared__ __align__(8) uint64_t s_empty[NSTAGES];
    __shared__ __align__(8) uint64_t s_done;

    const uint32_t rank = cluster_rank();

    if (wid == 0) {
        TCGEN05_ALLOC(smem_u32(s_tmem_ptr), 128);
        TCGEN05_RELINQ();
    }
    if (tid == 0) {
#pragma unroll
        for (int j = 0; j < NSTAGES; ++j) {
            MBARRIER_INIT(smem_u32(&s_full[j]), 1);
            MBARRIER_INIT(smem_u32(&s_empty[j]), 2);   // both CTAs' commits
        }
        MBARRIER_INIT(smem_u32(&s_done), 2);
    }
    __syncthreads();
    // peer barriers must be live before any multicast targets them
    CLUSTER_SYNC();

    uint32_t tmem_base;
    asm volatile("ld.shared.b32 %0, [%1];" : "=r"(tmem_base) : "r"(smem_u32(s_tmem_ptr)));

    if (wid == 0 && elect_one_pred()) {
        uint32_t fa[NSTAGES], ea[NSTAGES];
#pragma unroll
        for (int j = 0; j < NSTAGES; ++j) {
            fa[j] = smem_u32(&s_full[j]);
            ea[j] = smem_u32(&s_empty[j]);
        }
        const char* pAhi = (const char*)Ahi + (size_t)pm * (8 * TILE_BYTES);
        const char* pAlo = (const char*)Alo + (size_t)pm * (8 * TILE_BYTES);
        const char* pBhi = (const char*)Bhi + (size_t)pn * (8 * TILE_BYTES);
        const char* pBlo = (const char*)Blo + (size_t)pn * (8 * TILE_BYTES);

        // A multicast by rank 0 (delivers data + tx to BOTH CTAs); B unicast.
        auto load_chunk = [&](int ch, int st) {
            const uint32_t sb = sbase + st * STAGE_BYTES;
            const uint32_t mb = fa[st];
            MBARRIER_EXPECT_TX(mb, STAGE_BYTES);   // 64KB: 32KB mcast A + 32KB own B
            const size_t o = (size_t)ch * TILE_BYTES;
            if (rank == 0) {
                cp_bulk_mc(sb,              pAhi + o, TILE_BYTES, mb, 0x3);
                cp_bulk_mc(sb + TILE_BYTES, pAlo + o, TILE_BYTES, mb, 0x3);
            }
            cp_bulk(sb + 2 * TILE_BYTES, pBhi + o, TILE_BYTES, mb);
            cp_bulk(sb + 3 * TILE_BYTES, pBlo + o, TILE_BYTES, mb);
        };

        load_chunk(0, 0);
        load_chunk(1, 1);
        load_chunk(2, 2);

        int fph[NSTAGES] = {0, 0, 0};
        int eph[NSTAGES] = {0, 0, 0};

        for (int c = 0; c < NCHUNKS; ++c) {
            const int st = c % NSTAGES;
            MBARRIER_WAIT_PARITY(fa[st], fph[st]);
            fph[st] ^= 1;

            const uint32_t sb = sbase + st * STAGE_BYTES;
            const uint64_t dAhi = MAKE_SMEM_DESC(sb);
            const uint64_t dAlo = MAKE_SMEM_DESC(sb + TILE_BYTES);
            const uint64_t dBhi = MAKE_SMEM_DESC(sb + 2 * TILE_BYTES);
            const uint64_t dBlo = MAKE_SMEM_DESC(sb + 3 * TILE_BYTES);
#pragma unroll
            for (int s = 0; s < 4; ++s) {
                const bool first = (c == 0) && (s == 0);
                mma_bf16_ss(tmem_base, dAhi + 2 * s, dBhi + 2 * s, MMA_IDESC, !first);
                mma_bf16_ss(tmem_base, dAhi + 2 * s, dBlo + 2 * s, MMA_IDESC, true);
                mma_bf16_ss(tmem_base, dAlo + 2 * s, dBhi + 2 * s, MMA_IDESC, true);
            }
            if (c + NSTAGES < NCHUNKS) {
                // commit arrives on BOTH CTAs' empty[st]; stage freed only when
                // both CTAs' MMAs for chunk c completed (A buffer shared via mcast)
                TCGEN05_COMMIT_MC(ea[st], 0x3);
                MBARRIER_WAIT_PARITY(ea[st], eph[st]);
                eph[st] ^= 1;
                load_chunk(c + NSTAGES, st);
            } else if (c == NCHUNKS - 1) {
                TCGEN05_COMMIT_MC(smem_u32(&s_done), 0x3);
            }
        }
    }

    MBARRIER_WAIT_PARITY(smem_u32(&s_done), 0);
    TCGEN05_FENCE_AFTER();

    {
        const int rsub = (wid & 3) << 5;
        const int colh = (wid >> 2) << 6;
        const int m = m0 + rsub + lane;
        bool zero = false;
        if (EPI) zero = (post_mask[m] != 0);
        float* crow = C + (size_t)m * ldc + n0;

#pragma unroll
        for (int half = 0; half < 2; ++half) {
            const int cbase = colh + half * 32;
            uint32_t r[32];
            TCGEN05_LD_32X32B_X32(r, tmem_base + cbase);
            TCGEN05_WAIT_LD();
#pragma unroll
            for (int j = 0; j < 32; j += 4) {
                float4 v;
                v.x = __uint_as_float(r[j + 0]);
                v.y = __uint_as_float(r[j + 1]);
                v.z = __uint_as_float(r[j + 2]);
                v.w = __uint_as_float(r[j + 3]);
                if (EPI) {
                    const int n = n0 + cbase + j;
                    v.x += bias[n + 0];
                    v.y += bias[n + 1];
                    v.z += bias[n + 2];
                    v.w += bias[n + 3];
                    if (zero) { v.x = 0.f; v.y = 0.f; v.z = 0.f; v.w = 0.f; }
                }
                *(float4*)(crow + cbase + j) = v;
            }
        }
        TCGEN05_FENCE_BEFORE();
    }

    __syncthreads();
    if (tid == 0) {
#pragma unroll
        for (int j = 0; j < NSTAGES; ++j) {
            MBARRIER_INVAL(smem_u32(&s_full[j]));
            MBARRIER_INVAL(smem_u32(&s_empty[j]));
        }
        MBARRIER_INVAL(smem_u32(&s_done));
    }
    __syncthreads();
    if (wid == 0) TCGEN05_DEALLOC(tmem_base, 128);
    // no CTA may exit while peer multicast could still target it
    CLUSTER_SYNC();

#else
    // =========================== mma.sync fallback ==========================
    const int wm = (wid & 1) << 6;
    const int wn = (wid >> 1) << 5;

    auto issue_loads = [&](int ch, int st) {
        const uint32_t sb = sbase + st * STAGE_BYTES;
        const char* pA0 = (const char*)Ahi + ((size_t)pm * 8 + ch) * TILE_BYTES;
        const char* pA1 = (const char*)Alo + ((size_t)pm * 8 + ch) * TILE_BYTES;
        const char* pB0 = (const char*)Bhi + ((size_t)pn * 8 + ch) * TILE_BYTES;
        const char* pB1 = (const char*)Blo + ((size_t)pn * 8 + ch) * TILE_BYTES;
#pragma unroll
        for (int i = 0; i < 4; ++i) {
            const uint32_t u = (tid + (i << 8)) << 4;
            cp16(sb + u, pA0 + u);
            cp16(sb + TILE_BYTES + u, pA1 + u);
            cp16(sb + 2 * TILE_BYTES + u, pB0 + u);
            cp16(sb + 3 * TILE_BYTES + u, pB1 + u);
        }
        asm volatile("cp.async.commit_group;" ::: "memory");
    };

    float acc[4][4][4];
#pragma unroll
    for (int a = 0; a < 4; ++a)
#pragma unroll
        for (int b = 0; b < 4; ++b)
#pragma unroll
            for (int d = 0; d < 4; ++d) acc[a][b][d] = 0.f;

    issue_loads(0, 0);
    issue_loads(1, 1);

    for (int c = 0; c < NCHUNKS; ++c) {
        if (c < NCHUNKS - 1) asm volatile("cp.async.wait_group 1;" ::: "memory");
        else                 asm volatile("cp.async.wait_group 0;" ::: "memory");
        __syncthreads();
        const uint32_t sb = sbase + (c & 1) * STAGE_BYTES;

#pragma unroll
        for (int ks = 0; ks < 4; ++ks) {
            uint32_t ahi[4][4], alo[4][4];
#pragma unroll
            for (int mf = 0; mf < 4; ++mf) {
                const uint32_t row = wm + (mf << 4) + (lane & 15);
                const uint32_t kp = (ks << 1) + (lane >> 4);
                const uint32_t off = (row << 7) + (kp << 4);
                const uint32_t sw = off ^ ((off >> 3) & 0x70);
                ldsm4(ahi[mf], sb + sw);
                ldsm4(alo[mf], sb + TILE_BYTES + sw);
            }
            uint32_t bhi[4][2], blo[4][2];
#pragma unroll
            for (int nb = 0; nb < 2; ++nb) {
                const uint32_t row = wn + (nb << 4) + ((lane >> 4) << 3) + (lane & 7);
                const uint32_t kp = (ks << 1) + ((lane >> 3) & 1);
                const uint32_t off = (row << 7) + (kp << 4);
                const uint32_t sw = off ^ ((off >> 3) & 0x70);
                uint32_t t[4];
                ldsm4(t, sb + 2 * TILE_BYTES + sw);
                bhi[2 * nb][0] = t[0]; bhi[2 * nb][1] = t[1];
                bhi[2 * nb + 1][0] = t[2]; bhi[2 * nb + 1][1] = t[3];
                ldsm4(t, sb + 3 * TILE_BYTES + sw);
                blo[2 * nb][0] = t[0]; blo[2 * nb][1] = t[1];
                blo[2 * nb + 1][0] = t[2]; blo[2 * nb + 1][1] = t[3];
            }
#pragma unroll
            for (int mf = 0; mf < 4; ++mf)
#pragma unroll
                for (int nf = 0; nf < 4; ++nf) {
                    mma_bf16(acc[mf][nf], ahi[mf], bhi[nf]);
                    mma_bf16(acc[mf][nf], ahi[mf], blo[nf]);
                    mma_bf16(acc[mf][nf], alo[mf], bhi[nf]);
                }
        }
        __syncthreads();
        if (c + 2 < NCHUNKS) issue_loads(c + 2, (c + 2) & 1);
    }

#pragma unroll
    for (int mf = 0; mf < 4; ++mf) {
#pragma unroll
        for (int half = 0; half < 2; ++half) {
            const int m = m0 + wm + (mf << 4) + (half << 3) + (lane >> 2);
            bool zero = false;
            if (EPI) zero = (post_mask[m] != 0);
            float* crow = C + (size_t)m * ldc;
#pragma unroll
            for (int nf = 0; nf < 4; ++nf) {
                const int col = n0 + wn + (nf << 3) + ((lane & 3) << 1);
                float v0 = acc[mf][nf][half * 2 + 0];
                float v1 = acc[mf][nf][half * 2 + 1];
                if (EPI) {
                    v0 += bias[col];
                    v1 += bias[col + 1];
                    if (zero) { v0 = 0.f; v1 = 0.f; }
                }
                crow[col] = v0;
                crow[col + 1] = v1;
            }
        }
    }
#endif
}

// ---------------------------------------------------------------------------
// Splits: fp32 -> bf16 hi/lo into TILED+SWIZZLED layout.
// ---------------------------------------------------------------------------
__global__ void __launch_bounds__(256)
split_tiledA(const float* __restrict__ in, __nv_bfloat16* __restrict__ hi,
             __nv_bfloat16* __restrict__ lo, __nv_bfloat16* __restrict__ qhi,
             __nv_bfloat16* __restrict__ qlo, int Mtot, int withQ)
{
    int i = blockIdx.x * blockDim.x + threadIdx.x;
    const int units = Mtot << 6;
    if (i >= units) return;
    const int m = i >> 6;
    const int k = (i & 63) << 3;

    float x[8];
    const float* src = in + (size_t)m * GK + k;
#pragma unroll
    for (int j = 0; j < 8; ++j) x[j] = src[j];

    uint4 hv, lv;
    pack8(x, hv, lv);

    const size_t o = tiled_off(m, k);
    *(uint4*)((char*)hi + o) = hv;
    *(uint4*)((char*)lo + o) = lv;

    if (withQ && (m & 255) < 64) {
        const int mq = ((m >> 8) << 6) + (m & 63);
        const size_t oq = tiled_off(mq, k);
        *(uint4*)((char*)qhi + oq) = hv;
        *(uint4*)((char*)qlo + oq) = lv;
    }
}

__global__ void __launch_bounds__(256)
splitT_tiled(const float* __restrict__ in, __nv_bfloat16* __restrict__ hiT,
             __nv_bfloat16* __restrict__ loT, int Nd)
{
    int i = blockIdx.x * blockDim.x + threadIdx.x;
    const int units = Nd << 6;
    if (i >= units) return;
    const int n = i >> 6;
    const int k = (i & 63) << 3;

    float x[8];
#pragma unroll
    for (int j = 0; j < 8; ++j) x[j] = in[(size_t)(k + j) * Nd + n];
    uint4 hv, lv;
    pack8(x, hv, lv);

    const size_t o = tiled_off(n, k);
    *(uint4*)((char*)hiT + o) = hv;
    *(uint4*)((char*)loT + o) = lv;
}

// ---------------------------------------------------------------------------
// Attention (Round-9 proven): FFMA2 hot loops, direct tiled bf16 hi/lo output.
// ---------------------------------------------------------------------------
#define AQ_STRIDE 68
#define APT_STRIDE 68
#define A_SQ 0
#define A_SKV (64 * AQ_STRIDE)
#define A_SPT (A_SKV + 64 * 64)
#define A_SRED (A_SPT + 256 * APT_STRIDE)
#define A_SINV (A_SRED + 256)
#define ATTN_SMEM_FLOATS (A_SINV + 64)
#define ATTN_SMEM_BYTES (ATTN_SMEM_FLOATS * 4)

__global__ void __launch_bounds__(256, 2)
attn_kernel(const float* __restrict__ Q,
            const float* __restrict__ KV,
            const int* __restrict__ pre_mask,
            __nv_bfloat16* __restrict__ Ahi,
            __nv_bfloat16* __restrict__ Alo)
{
    extern __shared__ float sm[];
    float* sQ  = sm + A_SQ;
    float* sKV = sm + A_SKV;
    float* sPT = sm + A_SPT;
    float* sRed = sm + A_SRED;
    float* sInv = sm + A_SINV;

    const int tid = threadIdx.x;
    const int h = blockIdx.x;
    const int bs = blockIdx.y;
    const float NEG_INF = -INFINITY;

    {
        const int lr = tid >> 4;
        const int lc = (tid & 15) << 2;
#pragma unroll
        for (int it = 0; it < 4; ++it) {
            const int qi = lr + (it << 4);
            float4 v = *(const float4*)(Q + ((size_t)bs * NQ + qi) * EMBED_DIM + h * HEAD_DIM + lc);
            float* dst = &sQ[qi * AQ_STRIDE + lc];
            dst[0] = v.x * 0.125f;
            dst[1] = v.y * 0.125f;
            dst[2] = v.z * 0.125f;
            dst[3] = v.w * 0.125f;
        }
    }

    auto load_chunk = [&](const float* base) {
#pragma unroll
        for (int it = 0; it < 4; ++it) {
            const int idx = tid + (it << 8);
            const int e = idx >> 4;
            const int c = idx & 15;
            float4 v = *(const float4*)(base + (size_t)e * (2 * EMBED_DIM) + (c << 2));
            *(float4*)&sKV[(e << 6) + (((c + e) & 15) << 2)] = v;
        }
    };

    const int qg = tid >> 4;
    const int kt = tid & 15;

    for (int c4 = 0; c4 < 4; ++c4) {
        __syncthreads();
        load_chunk(KV + ((size_t)bs * NE + (c4 << 6)) * (2 * EMBED_DIM) + h * HEAD_DIM);
        __syncthreads();

#if HAS_TCGEN05
        unsigned long long accp[4][4];
#pragma unroll
        for (int i = 0; i < 4; ++i)
#pragma unroll
            for (int j = 0; j < 4; ++j) accp[i][j] = 0ull;

#pragma unroll
        for (int d4 = 0; d4 < 16; ++d4) {
            ulonglong2 q2[4];
#pragma unroll
            for (int i = 0; i < 4; ++i)
                q2[i] = *(const ulonglong2*)&sQ[((qg << 2) + i) * AQ_STRIDE + (d4 << 2)];
#pragma unroll
            for (int j = 0; j < 4; ++j) {
                const int e = kt + (j << 4);
                ulonglong2 k2 = *(const ulonglong2*)&sKV[(e << 6) + (((d4 + e) & 15) << 2)];
#pragma unroll
                for (int i = 0; i < 4; ++i) {
                    fma2(accp[i][j], q2[i].x, k2.x);
                    fma2(accp[i][j], q2[i].y, k2.y);
                }
            }
        }
#pragma unroll
        for (int j = 0; j < 4; ++j) {
            const int kglob = (c4 << 6) + kt + (j << 4);
            float4 v;
            v.x = lo32(accp[0][j]) + hi32(accp[0][j]);
            v.y = lo32(accp[1][j]) + hi32(accp[1][j]);
            v.z = lo32(accp[2][j]) + hi32(accp[2][j]);
            v.w = lo32(accp[3][j]) + hi32(accp[3][j]);
            *(float4*)&sPT[kglob * APT_STRIDE + (qg << 2)] = v;
        }
#else
        float acc[4][4];
#pragma unroll
        for (int i = 0; i < 4; ++i)
#pragma unroll
            for (int j = 0; j < 4; ++j) acc[i][j] = 0.f;

#pragma unroll
        for (int d4 = 0; d4 < 16; ++d4) {
            float4 q4[4];
#pragma unroll
            for (int i = 0; i < 4; ++i)
                q4[i] = *(const float4*)&sQ[((qg << 2) + i) * AQ_STRIDE + (d4 << 2)];
#pragma unroll
            for (int j = 0; j < 4; ++j) {
                const int e = kt + (j << 4);
                float4 k4 = *(const float4*)&sKV[(e << 6) + (((d4 + e) & 15) << 2)];
#pragma unroll
                for (int i = 0; i < 4; ++i) {
                    acc[i][j] = fmaf(q4[i].x, k4.x, acc[i][j]);
                    acc[i][j] = fmaf(q4[i].y, k4.y, acc[i][j]);
                    acc[i][j] = fmaf(q4[i].z, k4.z, acc[i][j]);
                    acc[i][j] = fmaf(q4[i].w, k4.w, acc[i][j]);
                }
            }
        }
#pragma unroll
        for (int j = 0; j < 4; ++j) {
            const int kglob = (c4 << 6) + kt + (j << 4);
            float4 v;
            v.x = acc[0][j]; v.y = acc[1][j]; v.z = acc[2][j]; v.w = acc[3][j];
            *(float4*)&sPT[kglob * APT_STRIDE + (qg << 2)] = v;
        }
#endif
    }
    __syncthreads();

    {
        const int row = tid >> 2;
        const int part = tid & 3;
        const int kbeg = part << 6;

        const int4* mrow = (const int4*)(pre_mask + ((size_t)bs * NQ + row) * NE + kbeg);
        uint64_t bits = 0;
#pragma unroll
        for (int g = 0; g < 16; ++g) {
            int4 m = mrow[g];
            uint64_t b = (uint64_t)(m.x != 0) | ((uint64_t)(m.y != 0) << 1) |
                         ((uint64_t)(m.z != 0) << 2) | ((uint64_t)(m.w != 0) << 3);
            bits |= b << (g << 2);
        }

        float mx = NEG_INF;
#pragma unroll 8
        for (int k = 0; k < 64; ++k) {
            if (!((bits >> k) & 1ull))
                mx = fmaxf(mx, sPT[(kbeg + k) * APT_STRIDE + row]);
        }
        sRed[(row << 2) + part] = mx;
        __syncthreads();
        const float rm = fmaxf(fmaxf(sRed[row << 2], sRed[(row << 2) + 1]),
                               fmaxf(sRed[(row << 2) + 2], sRed[(row << 2) + 3]));
        __syncthreads();

        const bool live = (rm != NEG_INF);
        float ssum = 0.f;
#pragma unroll 8
        for (int k = 0; k < 64; ++k) {
            float* p = &sPT[(kbeg + k) * APT_STRIDE + row];
            float e = 0.f;
            if (live && !((bits >> k) & 1ull)) e = __expf(*p - rm);
            *p = e;
            ssum += e;
        }
        sRed[(row << 2) + part] = ssum;
        __syncthreads();
        if (tid < 64) {
            const float t = sRed[tid << 2] + sRed[(tid << 2) + 1] +
                            sRed[(tid << 2) + 2] + sRed[(tid << 2) + 3];
            sInv[tid] = (t > 0.f) ? (1.f / t) : 0.f;
        }
    }

    const int qg2 = tid & 15;
    const int dg = tid >> 4;

#if HAS_TCGEN05
    unsigned long long accp2[4][2];
#pragma unroll
    for (int i = 0; i < 4; ++i) { accp2[i][0] = 0ull; accp2[i][1] = 0ull; }
#else
    float acc2[4][4];
#pragma unroll
    for (int i = 0; i < 4; ++i)
#pragma unroll
        for (int l = 0; l < 4; ++l) acc2[i][l] = 0.f;
#endif

    for (int c4 = 0; c4 < 4; ++c4) {
        __syncthreads();
        load_chunk(KV + ((size_t)bs * NE + (c4 << 6)) * (2 * EMBED_DIM) + EMBED_DIM + h * HEAD_DIM);
        __syncthreads();

#if HAS_TCGEN05
#pragma unroll 4
        for (int e = 0; e < 64; ++e) {
            const int kglob = (c4 << 6) + e;
            float4 w4 = *(const float4*)&sPT[kglob * APT_STRIDE + (qg2 << 2)];
            ulonglong2 v2 = *(const ulonglong2*)&sKV[(e << 6) + ((((dg) + e) & 15) << 2)];
            unsigned long long w0 = dup2(w4.x);
            unsigned long long w1 = dup2(w4.y);
            unsigned long long w2 = dup2(w4.z);
            unsigned long long w3 = dup2(w4.w);
            fma2(accp2[0][0], w0, v2.x);
            fma2(accp2[0][1], w0, v2.y);
            fma2(accp2[1][0], w1, v2.x);
            fma2(accp2[1][1], w1, v2.y);
            fma2(accp2[2][0], w2, v2.x);
            fma2(accp2[2][1], w2, v2.y);
            fma2(accp2[3][0], w3, v2.x);
            fma2(accp2[3][1], w3, v2.y);
        }
#else
#pragma unroll 4
        for (int e = 0; e < 64; ++e) {
            const int kglob = (c4 << 6) + e;
            float4 w4 = *(const float4*)&sPT[kglob * APT_STRIDE + (qg2 << 2)];
            float4 v4 = *(const float4*)&sKV[(e << 6) + ((((dg) + e) & 15) << 2)];
            acc2[0][0] = fmaf(w4.x, v4.x, acc2[0][0]);
            acc2[0][1] = fmaf(w4.x, v4.y, acc2[0][1]);
            acc2[0][2] = fmaf(w4.x, v4.z, acc2[0][2]);
            acc2[0][3] = fmaf(w4.x, v4.w, acc2[0][3]);
            acc2[1][0] = fmaf(w4.y, v4.x, acc2[1][0]);
            acc2[1][1] = fmaf(w4.y, v4.y, acc2[1][1]);
            acc2[1][2] = fmaf(w4.y, v4.z, acc2[1][2]);
            acc2[1][3] = fmaf(w4.y, v4.w, acc2[1][3]);
            acc2[2][0] = fmaf(w4.z, v4.x, acc2[2][0]);
            acc2[2][1] = fmaf(w4.z, v4.y, acc2[2][1]);
            acc2[2][2] = fmaf(w4.z, v4.z, acc2[2][2]);
            acc2[2][3] = fmaf(w4.z, v4.w, acc2[2][3]);
            acc2[3][0] = fmaf(w4.w, v4.x, acc2[3][0]);
            acc2[3][1] = fmaf(w4.w, v4.y, acc2[3][1]);
            acc2[3][2] = fmaf(w4.w, v4.z, acc2[3][2]);
            acc2[3][3] = fmaf(w4.w, v4.w, acc2[3][3]);
        }
#endif
    }

    const int k0 = h * HEAD_DIM + ((dg >> 1) << 3);
    const int sub = (dg & 1) << 3;
#pragma unroll
    for (int i = 0; i < 4; ++i) {
        const int qi = (qg2 << 2) + i;
        const float inv = sInv[qi];
        float x[4];
#if HAS_TCGEN05
        x[0] = lo32(accp2[i][0]) * inv;
        x[1] = hi32(accp2[i][0]) * inv;
        x[2] = lo32(accp2[i][1]) * inv;
        x[3] = hi32(accp2[i][1]) * inv;
#else
#pragma unroll
        for (int j = 0; j < 4; ++j) x[j] = acc2[i][j] * inv;
#endif
        uint2 hv, lv;
        pack4(x, hv, lv);
        const int m = bs * NQ + qi;
        const size_t o = tiled_off(m, k0) + sub;
        *(uint2*)((char*)Ahi + o) = hv;
        *(uint2*)((char*)Alo + o) = lv;
    }
}

// ---------------------------------------------------------------------------
// kernel_launch
// ---------------------------------------------------------------------------
extern "C" void kernel_launch(void* const* d_in, const int* in_sizes, int n_in,
                              void* d_out, int out_size)
{
    const float* entities  = (const float*)d_in[0];
    const int*   pre_mask  = (const int*)d_in[1];
    const int*   post_mask = (const int*)d_in[2];
    const float* W_in      = (const float*)d_in[3];
    const float* W_out     = (const float*)d_in[4];
    const float* b_out     = (const float*)d_in[5];
    float* out = (float*)d_out;

    float *Qs, *KVs;
    __nv_bfloat16 *eh, *el, *qh, *ql, *ah, *al, *wih, *wil, *woh, *wol;
    cudaGetSymbolAddress((void**)&Qs, g_Q);
    cudaGetSymbolAddress((void**)&KVs, g_KV);
    cudaGetSymbolAddress((void**)&eh, g_ent_hi);
    cudaGetSymbolAddress((void**)&el, g_ent_lo);
    cudaGetSymbolAddress((void**)&qh, g_q_hi);
    cudaGetSymbolAddress((void**)&ql, g_q_lo);
    cudaGetSymbolAddress((void**)&ah, g_attn_hi);
    cudaGetSymbolAddress((void**)&al, g_attn_lo);
    cudaGetSymbolAddress((void**)&wih, g_WinT_hi);
    cudaGetSymbolAddress((void**)&wil, g_WinT_lo);
    cudaGetSymbolAddress((void**)&woh, g_WoutT_hi);
    cudaGetSymbolAddress((void**)&wol, g_WoutT_lo);

    cudaFuncSetAttribute(gemm_bf16x3<false>,
                         cudaFuncAttributeMaxDynamicSharedMemorySize, GEMM_DYN_SMEM);
    cudaFuncSetAttribute(gemm_bf16x3<true>,
                         cudaFuncAttributeMaxDynamicSharedMemorySize, GEMM_DYN_SMEM);
    cudaFuncSetAttribute(attn_kernel,
                         cudaFuncAttributeMaxDynamicSharedMemorySize, ATTN_SMEM_BYTES);

    // 1) split entities -> tiled bf16 hi/lo (+ compact Q rows)
    {
        int units = (BS * NE) << 6;
        split_tiledA<<<(units + 255) / 256, 256>>>(entities, eh, el, qh, ql, BS * NE, 1);
    }
    // 2) split+transpose weights -> tiled
    {
        int u1 = QKV_DIM << 6;
        splitT_tiled<<<(u1 + 255) / 256, 256>>>(W_in, wih, wil, QKV_DIM);
        int u2 = OUT_DIM << 6;
        splitT_tiled<<<(u2 + 255) / 256, 256>>>(W_out, woh, wol, OUT_DIM);
    }
    // 3) Q = q_ent @ W_in[:, 0:512]     M=32768, N=512  (gridDim.x=4, cluster 2)
    gemm_bf16x3<false><<<dim3(EMBED_DIM / 128, (BS * NQ) / 128), 256, GEMM_DYN_SMEM>>>(
        qh, ql, wih, wil, Qs, EMBED_DIM, nullptr, nullptr);

    // 4) KV = entities @ W_in[:, 512:1536]  M=131072, N=1024 (gridDim.x=8, cluster 2)
    gemm_bf16x3<false><<<dim3((2 * EMBED_DIM) / 128, (BS * NE) / 128), 256, GEMM_DYN_SMEM>>>(
        eh, el, wih + 262144, wil + 262144, KVs, 2 * EMBED_DIM, nullptr, nullptr);

    // 5) attention (writes tiled bf16 hi/lo directly)
    attn_kernel<<<dim3(N_HEADS, BS), 256, ATTN_SMEM_BYTES>>>(Qs, KVs, pre_mask, ah, al);

    // 6) out = ATTN @ W_out + b_out, post-masked   M=32768, N=512 (cluster 2)
    gemm_bf16x3<true><<<dim3(OUT_DIM / 128, (BS * NQ) / 128), 256, GEMM_DYN_SMEM>>>(
        ah, al, woh, wol, out, OUT_DIM, b_out, post_mask);
}

// round 12
// speedup vs baseline: 1.2997x; 1.2997x over previous
#include <cuda_runtime.h>
#include <cuda_bf16.h>
#include <cuda_fp16.h>
#include <math.h>
#include <stdint.h>

// Problem constants
#define BS 512
#define NE 256
#define NQ 64
#define IN_DIM 512
#define EMBED_DIM 512
#define OUT_DIM 512
#define N_HEADS 8
#define HEAD_DIM 64
#define QKV_DIM (3 * EMBED_DIM)

// Arch-feature gate: tcgen05 / f32x2 only exist in arch-specific passes.
#if defined(__CUDA_ARCH__) && (defined(__CUDA_ARCH_FEAT_SM103_ALL) || defined(__CUDA_ARCH_FEAT_SM100_ALL) || defined(__CUDA_ARCH_FEAT_SM101_ALL))
#define HAS_TCGEN05 1
#else
#define HAS_TCGEN05 0
#endif

// ---------------------------------------------------------------------------
// Scratch (device globals). GEMM operands live in TILE-CONTIGUOUS,
// PRE-SWIZZLED (SW128) layout: [M/128 panels][8 K-chunks][16384 bytes], fp16.
// ---------------------------------------------------------------------------
__device__ float g_Q[(size_t)BS * NQ * EMBED_DIM];
__device__ float g_KV[(size_t)BS * NE * (2 * EMBED_DIM)];
__device__ __align__(1024) __half g_ent_h[(size_t)BS * NE * IN_DIM];
__device__ __align__(1024) __half g_q_h[(size_t)BS * NQ * IN_DIM];
__device__ __align__(1024) __half g_attn_h[(size_t)BS * NQ * EMBED_DIM];
__device__ __align__(1024) __half g_WinT_h[(size_t)QKV_DIM * IN_DIM];
__device__ __align__(1024) __half g_WoutT_h[(size_t)OUT_DIM * EMBED_DIM];

// ---------------------------------------------------------------------------
// Common helpers
// ---------------------------------------------------------------------------
__device__ __forceinline__ uint32_t smem_u32(const void* p) {
    uint32_t a;
    asm("{ .reg .u64 t; cvta.to.shared.u64 t, %1; cvt.u32.u64 %0, t; }" : "=r"(a) : "l"(p));
    return a;
}
__device__ __forceinline__ void cp16(uint32_t s, const void* g) {
    asm volatile("cp.async.cg.shared.global [%0], [%1], 16;" :: "r"(s), "l"(g) : "memory");
}
__device__ __forceinline__ void ldsm4(uint32_t* r, uint32_t addr) {
    asm volatile("ldmatrix.sync.aligned.m8n8.x4.shared.b16 {%0,%1,%2,%3}, [%4];"
                 : "=r"(r[0]), "=r"(r[1]), "=r"(r[2]), "=r"(r[3]) : "r"(addr));
}
__device__ __forceinline__ void mma_fp16(float* d, const uint32_t* a, const uint32_t* b) {
    asm volatile("mma.sync.aligned.m16n8k16.row.col.f32.f16.f16.f32 "
                 "{%0,%1,%2,%3}, {%4,%5,%6,%7}, {%8,%9}, {%0,%1,%2,%3};"
                 : "+f"(d[0]), "+f"(d[1]), "+f"(d[2]), "+f"(d[3])
                 : "r"(a[0]), "r"(a[1]), "r"(a[2]), "r"(a[3]), "r"(b[0]), "r"(b[1]));
}

// fp32[8] -> fp16 packed 16B unit
__device__ __forceinline__ void pack8h(const float* src, uint4& hv) {
    uint32_t* hp = (uint32_t*)&hv;
#pragma unroll
    for (int j = 0; j < 4; ++j) {
        __half2 h2;
        h2.x = __float2half(src[2 * j]);
        h2.y = __float2half(src[2 * j + 1]);
        hp[j] = *(uint32_t*)&h2;
    }
}
// fp32[4] -> fp16 packed 8B unit
__device__ __forceinline__ void pack4h(const float* src, uint2& hv) {
    uint32_t* hp = (uint32_t*)&hv;
#pragma unroll
    for (int j = 0; j < 2; ++j) {
        __half2 h2;
        h2.x = __float2half(src[2 * j]);
        h2.y = __float2half(src[2 * j + 1]);
        hp[j] = *(uint32_t*)&h2;
    }
}

// byte offset of (m, k) in tiled+swizzled layout (k multiple of 8)
__device__ __forceinline__ size_t tiled_off(int m, int k) {
    const int panel = m >> 7, r = m & 127, ch = k >> 6;
    uint32_t off = (uint32_t)(r << 7) + ((k & 63) << 1);
    off = off ^ ((off >> 3) & 0x70);
    return ((size_t)(panel * 8 + ch) << 14) + off;
}

#if HAS_TCGEN05
// ---------------------------------------------------------------------------
// tcgen05 + bulk-async + f32x2 helpers (arch-specific pass only)
// ---------------------------------------------------------------------------
__device__ __forceinline__ uint32_t elect_one_pred() {
    uint32_t p;
    asm volatile("{\n\t.reg .pred p;\n\telect.sync _|p, 0xFFFFFFFF;\n\tselp.b32 %0, 1, 0, p;\n\t}" : "=r"(p));
    return p;
}
#define TCGEN05_ALLOC(sa, n) \
    asm volatile("tcgen05.alloc.cta_group::1.sync.aligned.shared::cta.b32 [%0], %1;" :: "r"((uint32_t)(sa)), "r"((uint32_t)(n)) : "memory")
#define TCGEN05_DEALLOC(t, n) \
    asm volatile("tcgen05.dealloc.cta_group::1.sync.aligned.b32 %0, %1;" :: "r"(t), "r"((uint32_t)(n)))
#define TCGEN05_RELINQ() \
    asm volatile("tcgen05.relinquish_alloc_permit.cta_group::1.sync.aligned;")
#define TCGEN05_COMMIT(mb) \
    asm volatile("tcgen05.commit.cta_group::1.mbarrier::arrive::one.shared::cluster.b64 [%0];" :: "r"((uint32_t)(mb)) : "memory")
#define TCGEN05_FENCE_AFTER() asm volatile("tcgen05.fence::after_thread_sync;" ::: "memory")
#define TCGEN05_FENCE_BEFORE() asm volatile("tcgen05.fence::before_thread_sync;" ::: "memory")
#define TCGEN05_WAIT_LD() asm volatile("tcgen05.wait::ld.sync.aligned;" ::: "memory")
#define MBARRIER_INIT(mb, cnt) \
    asm volatile("mbarrier.init.shared.b64 [%0], %1;" :: "r"((uint32_t)(mb)), "r"((uint32_t)(cnt)) : "memory")
#define MBARRIER_INVAL(mb) \
    asm volatile("mbarrier.inval.shared.b64 [%0];" :: "r"((uint32_t)(mb)) : "memory")
#define MBARRIER_EXPECT_TX(mb, tx) \
    asm volatile("mbarrier.arrive.expect_tx.shared.b64 _, [%0], %1;" :: "r"((uint32_t)(mb)), "r"((uint32_t)(tx)) : "memory")
#define MBARRIER_WAIT_PARITY(mb, par) do {                                           \
    uint32_t _mb = (uint32_t)(mb); uint32_t _p = (uint32_t)(par); uint32_t _d;       \
    asm volatile("{\n\t.reg .pred p;\n\t"                                            \
        "mbarrier.try_wait.parity.acquire.cta.shared::cta.b64 p, [%1], %2;\n\t"      \
        "selp.b32 %0, 1, 0, p;\n\t}" : "=r"(_d) : "r"(_mb), "r"(_p) : "memory");     \
    if (!_d) {                                                                       \
        asm volatile("{\n\t.reg .pred P1;\n\t"                                       \
            "WL_%=:\n\t"                                                             \
            "mbarrier.try_wait.parity.acquire.cta.shared::cta.b64 P1, [%0], %1, 0x989680;\n\t" \
            "@P1 bra.uni WD_%=;\n\t"                                                 \
            "bra.uni WL_%=;\n\t"                                                     \
            "WD_%=:\n\t}" :: "r"(_mb), "r"(_p) : "memory");                          \
    }                                                                                \
} while (0)

__device__ __forceinline__ void cp_bulk(uint32_t dst, const void* src, uint32_t bytes, uint32_t mb) {
    asm volatile("cp.async.bulk.shared::cta.global.mbarrier::complete_tx::bytes [%0], [%1], %2, [%3];"
                 :: "r"(dst), "l"(src), "r"(bytes), "r"(mb) : "memory");
}

#define TCGEN05_LD_32X32B_X32(r, ta) \
    asm volatile( \
        "tcgen05.ld.sync.aligned.32x32b.x32.b32 " \
        "{%0, %1, %2, %3, %4, %5, %6, %7, " \
        " %8, %9, %10, %11, %12, %13, %14, %15, " \
        " %16, %17, %18, %19, %20, %21, %22, %23, " \
        " %24, %25, %26, %27, %28, %29, %30, %31}, [%32];" \
        : "=r"((r)[0]),  "=r"((r)[1]),  "=r"((r)[2]),  "=r"((r)[3]), \
          "=r"((r)[4]),  "=r"((r)[5]),  "=r"((r)[6]),  "=r"((r)[7]), \
          "=r"((r)[8]),  "=r"((r)[9]),  "=r"((r)[10]), "=r"((r)[11]), \
          "=r"((r)[12]), "=r"((r)[13]), "=r"((r)[14]), "=r"((r)[15]), \
          "=r"((r)[16]), "=r"((r)[17]), "=r"((r)[18]), "=r"((r)[19]), \
          "=r"((r)[20]), "=r"((r)[21]), "=r"((r)[22]), "=r"((r)[23]), \
          "=r"((r)[24]), "=r"((r)[25]), "=r"((r)[26]), "=r"((r)[27]), \
          "=r"((r)[28]), "=r"((r)[29]), "=r"((r)[30]), "=r"((r)[31]) \
        : "r"(ta))

static constexpr uint64_t SMEM_DESC_BASE_SW128 =
    (uint64_t(2) << 61) | (uint64_t(1) << 46) | (uint64_t(64) << 32) | (uint64_t(1) << 16);
#define MAKE_SMEM_DESC(ba) (SMEM_DESC_BASE_SW128 | ((uint64_t)((ba) >> 4) & 0x3FFF))

// Proven operand binding: %3 = idesc, %4 = enable, %5 = zero reg.
__device__ __forceinline__ void mma_f16_ss(uint32_t d, uint64_t da, uint64_t db,
                                           uint32_t idesc, bool en) {
    uint32_t e = en ? 1u : 0u;
    asm volatile(
        "{\n\t.reg .pred p;\n\t"
        "setp.ne.u32 p, %4, 0;\n\t"
        "tcgen05.mma.cta_group::1.kind::f16 [%0], %1, %2, %3, {%5, %5, %5, %5}, p;\n\t"
        "}"
        :: "r"(d), "l"(da), "l"(db), "r"(idesc), "r"(e), "r"(0u)
        : "memory");
}
// idesc: f32 accum, FP16 a (0), FP16 b (0), N=128, M=128
static constexpr uint32_t MMA_IDESC =
    (1u << 4) | ((128u / 8) << 17) | ((128u / 16) << 24);

// packed fp32x2 FMA (FFMA2)
__device__ __forceinline__ void fma2(unsigned long long& d,
                                     unsigned long long a, unsigned long long b) {
    asm("fma.rn.f32x2 %0, %1, %2, %0;" : "+l"(d) : "l"(a), "l"(b));
}
__device__ __forceinline__ unsigned long long dup2(float w) {
    unsigned long long r;
    asm("mov.b64 %0, {%1, %1};" : "=l"(r) : "r"(__float_as_uint(w)));
    return r;
}
__device__ __forceinline__ float lo32(unsigned long long a) {
    return __uint_as_float((uint32_t)a);
}
__device__ __forceinline__ float hi32(unsigned long long a) {
    return __uint_as_float((uint32_t)(a >> 32));
}
#endif // HAS_TCGEN05

#define GK 512
#define NCHUNKS 8
#define TILE_BYTES 16384

// ---------------------------------------------------------------------------
// fp16 GEMM: 128x128 tile, 3-stage pipeline (Round-9 structure), single
// product per K-step. Stage = A|B = 32KB; 3 stages = 96KB -> 2 CTAs/SM.
// ---------------------------------------------------------------------------
#define STAGE_BYTES (2 * TILE_BYTES)
#define NSTAGES 3
#define GEMM_DYN_SMEM (NSTAGES * STAGE_BYTES + 1024)

template <bool EPI>
__global__ void __launch_bounds__(256)
gemm_fp16(const __half* __restrict__ A, const __half* __restrict__ B,
          float* __restrict__ C, int ldc,
          const float* __restrict__ bias, const int* __restrict__ post_mask)
{
    extern __shared__ char dyn_smem[];
    const int tid = threadIdx.x;
    const int wid = tid >> 5;
    const int lane = tid & 31;
    const int m0 = blockIdx.y << 7;
    const int n0 = blockIdx.x << 7;
    const int pm = blockIdx.y;
    const int pn = blockIdx.x;

    const uint32_t sbase = (smem_u32(dyn_smem) + 1023u) & ~1023u;

#if HAS_TCGEN05
    __shared__ uint32_t s_tmem_ptr[2];
    __shared__ __align__(8) uint64_t s_full[NSTAGES];
    __shared__ __align__(8) uint64_t s_empty[NSTAGES];
    __shared__ __align__(8) uint64_t s_done;

    if (wid == 0) {
        TCGEN05_ALLOC(smem_u32(s_tmem_ptr), 128);
        TCGEN05_RELINQ();
    }
    if (tid == 0) {
#pragma unroll
        for (int j = 0; j < NSTAGES; ++j) {
            MBARRIER_INIT(smem_u32(&s_full[j]), 1);
            MBARRIER_INIT(smem_u32(&s_empty[j]), 1);
        }
        MBARRIER_INIT(smem_u32(&s_done), 1);
    }
    __syncthreads();

    uint32_t tmem_base;
    asm volatile("ld.shared.b32 %0, [%1];" : "=r"(tmem_base) : "r"(smem_u32(s_tmem_ptr)));

    if (wid == 0 && elect_one_pred()) {
        uint32_t fa[NSTAGES], ea[NSTAGES];
#pragma unroll
        for (int j = 0; j < NSTAGES; ++j) {
            fa[j] = smem_u32(&s_full[j]);
            ea[j] = smem_u32(&s_empty[j]);
        }
        const char* pA = (const char*)A + (size_t)pm * (8 * TILE_BYTES);
        const char* pB = (const char*)B + (size_t)pn * (8 * TILE_BYTES);

        auto load_chunk = [&](int ch, int st) {
            const uint32_t sb = sbase + st * STAGE_BYTES;
            const uint32_t mb = fa[st];
            MBARRIER_EXPECT_TX(mb, STAGE_BYTES);
            const size_t o = (size_t)ch * TILE_BYTES;
            cp_bulk(sb,              pA + o, TILE_BYTES, mb);
            cp_bulk(sb + TILE_BYTES, pB + o, TILE_BYTES, mb);
        };

        load_chunk(0, 0);
        load_chunk(1, 1);
        load_chunk(2, 2);

        int fph[NSTAGES] = {0, 0, 0};
        int eph[NSTAGES] = {0, 0, 0};

        for (int c = 0; c < NCHUNKS; ++c) {
            const int st = c % NSTAGES;
            MBARRIER_WAIT_PARITY(fa[st], fph[st]);
            fph[st] ^= 1;

            const uint32_t sb = sbase + st * STAGE_BYTES;
            const uint64_t dA = MAKE_SMEM_DESC(sb);
            const uint64_t dB = MAKE_SMEM_DESC(sb + TILE_BYTES);
#pragma unroll
            for (int s = 0; s < 4; ++s) {
                const bool first = (c == 0) && (s == 0);
                mma_f16_ss(tmem_base, dA + 2 * s, dB + 2 * s, MMA_IDESC, !first);
            }
            if (c + NSTAGES < NCHUNKS) {
                TCGEN05_COMMIT(ea[st]);
                MBARRIER_WAIT_PARITY(ea[st], eph[st]);
                eph[st] ^= 1;
                load_chunk(c + NSTAGES, st);
            } else if (c == NCHUNKS - 1) {
                TCGEN05_COMMIT(smem_u32(&s_done));
            }
        }
    }

    MBARRIER_WAIT_PARITY(smem_u32(&s_done), 0);
    TCGEN05_FENCE_AFTER();

    // epilogue: warp (wid&3) -> 32-row subpartition, (wid>>2) -> column half
    {
        const int rsub = (wid & 3) << 5;
        const int colh = (wid >> 2) << 6;
        const int m = m0 + rsub + lane;
        bool zero = false;
        if (EPI) zero = (post_mask[m] != 0);
        float* crow = C + (size_t)m * ldc + n0;

#pragma unroll
        for (int half = 0; half < 2; ++half) {
            const int cbase = colh + half * 32;
            uint32_t r[32];
            TCGEN05_LD_32X32B_X32(r, tmem_base + cbase);
            TCGEN05_WAIT_LD();
#pragma unroll
            for (int j = 0; j < 32; j += 4) {
                float4 v;
                v.x = __uint_as_float(r[j + 0]);
                v.y = __uint_as_float(r[j + 1]);
                v.z = __uint_as_float(r[j + 2]);
                v.w = __uint_as_float(r[j + 3]);
                if (EPI) {
                    const int n = n0 + cbase + j;
                    v.x += bias[n + 0];
                    v.y += bias[n + 1];
                    v.z += bias[n + 2];
                    v.w += bias[n + 3];
                    if (zero) { v.x = 0.f; v.y = 0.f; v.z = 0.f; v.w = 0.f; }
                }
                *(float4*)(crow + cbase + j) = v;
            }
        }
        TCGEN05_FENCE_BEFORE();
    }

    __syncthreads();
    if (tid == 0) {
#pragma unroll
        for (int j = 0; j < NSTAGES; ++j) {
            MBARRIER_INVAL(smem_u32(&s_full[j]));
            MBARRIER_INVAL(smem_u32(&s_empty[j]));
        }
        MBARRIER_INVAL(smem_u32(&s_done));
    }
    __syncthreads();
    if (wid == 0) TCGEN05_DEALLOC(tmem_base, 128);

#else
    // =========================== mma.sync fallback ==========================
    const int wm = (wid & 1) << 6;
    const int wn = (wid >> 1) << 5;

    auto issue_loads = [&](int ch, int st) {
        const uint32_t sb = sbase + st * STAGE_BYTES;
        const char* pA = (const char*)A + ((size_t)pm * 8 + ch) * TILE_BYTES;
        const char* pB = (const char*)B + ((size_t)pn * 8 + ch) * TILE_BYTES;
#pragma unroll
        for (int i = 0; i < 4; ++i) {
            const uint32_t u = (tid + (i << 8)) << 4;
            cp16(sb + u, pA + u);
            cp16(sb + TILE_BYTES + u, pB + u);
        }
        asm volatile("cp.async.commit_group;" ::: "memory");
    };

    float acc[4][4][4];
#pragma unroll
    for (int a = 0; a < 4; ++a)
#pragma unroll
        for (int b = 0; b < 4; ++b)
#pragma unroll
            for (int d = 0; d < 4; ++d) acc[a][b][d] = 0.f;

    issue_loads(0, 0);
    issue_loads(1, 1);

    for (int c = 0; c < NCHUNKS; ++c) {
        if (c < NCHUNKS - 1) asm volatile("cp.async.wait_group 1;" ::: "memory");
        else                 asm volatile("cp.async.wait_group 0;" ::: "memory");
        __syncthreads();
        const uint32_t sb = sbase + (c & 1) * STAGE_BYTES;

#pragma unroll
        for (int ks = 0; ks < 4; ++ks) {
            uint32_t av[4][4];
#pragma unroll
            for (int mf = 0; mf < 4; ++mf) {
                const uint32_t row = wm + (mf << 4) + (lane & 15);
                const uint32_t kp = (ks << 1) + (lane >> 4);
                const uint32_t off = (row << 7) + (kp << 4);
                const uint32_t sw = off ^ ((off >> 3) & 0x70);
                ldsm4(av[mf], sb + sw);
            }
            uint32_t bv[4][2];
#pragma unroll
            for (int nb = 0; nb < 2; ++nb) {
                const uint32_t row = wn + (nb << 4) + ((lane >> 4) << 3) + (lane & 7);
                const uint32_t kp = (ks << 1) + ((lane >> 3) & 1);
                const uint32_t off = (row << 7) + (kp << 4);
                const uint32_t sw = off ^ ((off >> 3) & 0x70);
                uint32_t t[4];
                ldsm4(t, sb + TILE_BYTES + sw);
                bv[2 * nb][0] = t[0]; bv[2 * nb][1] = t[1];
                bv[2 * nb + 1][0] = t[2]; bv[2 * nb + 1][1] = t[3];
            }
#pragma unroll
            for (int mf = 0; mf < 4; ++mf)
#pragma unroll
                for (int nf = 0; nf < 4; ++nf)
                    mma_fp16(acc[mf][nf], av[mf], bv[nf]);
        }
        __syncthreads();
        if (c + 2 < NCHUNKS) issue_loads(c + 2, (c + 2) & 1);
    }

#pragma unroll
    for (int mf = 0; mf < 4; ++mf) {
#pragma unroll
        for (int half = 0; half < 2; ++half) {
            const int m = m0 + wm + (mf << 4) + (half << 3) + (lane >> 2);
            bool zero = false;
            if (EPI) zero = (post_mask[m] != 0);
            float* crow = C + (size_t)m * ldc;
#pragma unroll
            for (int nf = 0; nf < 4; ++nf) {
                const int col = n0 + wn + (nf << 3) + ((lane & 3) << 1);
                float v0 = acc[mf][nf][half * 2 + 0];
                float v1 = acc[mf][nf][half * 2 + 1];
                if (EPI) {
                    v0 += bias[col];
                    v1 += bias[col + 1];
                    if (zero) { v0 = 0.f; v1 = 0.f; }
                }
                crow[col] = v0;
                crow[col + 1] = v1;
            }
        }
    }
#endif
}

// ---------------------------------------------------------------------------
// Splits: fp32 -> fp16 into TILED+SWIZZLED layout.
// ---------------------------------------------------------------------------
__global__ void __launch_bounds__(256)
split_tiledA(const float* __restrict__ in, __half* __restrict__ hh,
             __half* __restrict__ qh, int Mtot, int withQ)
{
    int i = blockIdx.x * blockDim.x + threadIdx.x;
    const int units = Mtot << 6;
    if (i >= units) return;
    const int m = i >> 6;
    const int k = (i & 63) << 3;

    float x[8];
    const float* src = in + (size_t)m * GK + k;
#pragma unroll
    for (int j = 0; j < 8; ++j) x[j] = src[j];

    uint4 hv;
    pack8h(x, hv);

    const size_t o = tiled_off(m, k);
    *(uint4*)((char*)hh + o) = hv;

    if (withQ && (m & 255) < 64) {
        const int mq = ((m >> 8) << 6) + (m & 63);
        const size_t oq = tiled_off(mq, k);
        *(uint4*)((char*)qh + oq) = hv;
    }
}

__global__ void __launch_bounds__(256)
splitT_tiled(const float* __restrict__ in, __half* __restrict__ hT, int Nd)
{
    int i = blockIdx.x * blockDim.x + threadIdx.x;
    const int units = Nd << 6;
    if (i >= units) return;
    const int n = i >> 6;
    const int k = (i & 63) << 3;

    float x[8];
#pragma unroll
    for (int j = 0; j < 8; ++j) x[j] = in[(size_t)(k + j) * Nd + n];
    uint4 hv;
    pack8h(x, hv);

    const size_t o = tiled_off(n, k);
    *(uint4*)((char*)hT + o) = hv;
}

// ---------------------------------------------------------------------------
// Attention (Round-9 proven): FFMA2 hot loops, direct tiled fp16 output.
// ---------------------------------------------------------------------------
#define AQ_STRIDE 68
#define APT_STRIDE 68
#define A_SQ 0
#define A_SKV (64 * AQ_STRIDE)
#define A_SPT (A_SKV + 64 * 64)
#define A_SRED (A_SPT + 256 * APT_STRIDE)
#define A_SINV (A_SRED + 256)
#define ATTN_SMEM_FLOATS (A_SINV + 64)
#define ATTN_SMEM_BYTES (ATTN_SMEM_FLOATS * 4)

__global__ void __launch_bounds__(256, 2)
attn_kernel(const float* __restrict__ Q,
            const float* __restrict__ KV,
            const int* __restrict__ pre_mask,
            __half* __restrict__ Ah)
{
    extern __shared__ float sm[];
    float* sQ  = sm + A_SQ;
    float* sKV = sm + A_SKV;
    float* sPT = sm + A_SPT;
    float* sRed = sm + A_SRED;
    float* sInv = sm + A_SINV;

    const int tid = threadIdx.x;
    const int h = blockIdx.x;
    const int bs = blockIdx.y;
    const float NEG_INF = -INFINITY;

    {
        const int lr = tid >> 4;
        const int lc = (tid & 15) << 2;
#pragma unroll
        for (int it = 0; it < 4; ++it) {
            const int qi = lr + (it << 4);
            float4 v = *(const float4*)(Q + ((size_t)bs * NQ + qi) * EMBED_DIM + h * HEAD_DIM + lc);
            float* dst = &sQ[qi * AQ_STRIDE + lc];
            dst[0] = v.x * 0.125f;
            dst[1] = v.y * 0.125f;
            dst[2] = v.z * 0.125f;
            dst[3] = v.w * 0.125f;
        }
    }

    auto load_chunk = [&](const float* base) {
#pragma unroll
        for (int it = 0; it < 4; ++it) {
            const int idx = tid + (it << 8);
            const int e = idx >> 4;
            const int c = idx & 15;
            float4 v = *(const float4*)(base + (size_t)e * (2 * EMBED_DIM) + (c << 2));
            *(float4*)&sKV[(e << 6) + (((c + e) & 15) << 2)] = v;
        }
    };

    const int qg = tid >> 4;
    const int kt = tid & 15;

    for (int c4 = 0; c4 < 4; ++c4) {
        __syncthreads();
        load_chunk(KV + ((size_t)bs * NE + (c4 << 6)) * (2 * EMBED_DIM) + h * HEAD_DIM);
        __syncthreads();

#if HAS_TCGEN05
        unsigned long long accp[4][4];
#pragma unroll
        for (int i = 0; i < 4; ++i)
#pragma unroll
            for (int j = 0; j < 4; ++j) accp[i][j] = 0ull;

#pragma unroll
        for (int d4 = 0; d4 < 16; ++d4) {
            ulonglong2 q2[4];
#pragma unroll
            for (int i = 0; i < 4; ++i)
                q2[i] = *(const ulonglong2*)&sQ[((qg << 2) + i) * AQ_STRIDE + (d4 << 2)];
#pragma unroll
            for (int j = 0; j < 4; ++j) {
                const int e = kt + (j << 4);
                ulonglong2 k2 = *(const ulonglong2*)&sKV[(e << 6) + (((d4 + e) & 15) << 2)];
#pragma unroll
                for (int i = 0; i < 4; ++i) {
                    fma2(accp[i][j], q2[i].x, k2.x);
                    fma2(accp[i][j], q2[i].y, k2.y);
                }
            }
        }
#pragma unroll
        for (int j = 0; j < 4; ++j) {
            const int kglob = (c4 << 6) + kt + (j << 4);
            float4 v;
            v.x = lo32(accp[0][j]) + hi32(accp[0][j]);
            v.y = lo32(accp[1][j]) + hi32(accp[1][j]);
            v.z = lo32(accp[2][j]) + hi32(accp[2][j]);
            v.w = lo32(accp[3][j]) + hi32(accp[3][j]);
            *(float4*)&sPT[kglob * APT_STRIDE + (qg << 2)] = v;
        }
#else
        float acc[4][4];
#pragma unroll
        for (int i = 0; i < 4; ++i)
#pragma unroll
            for (int j = 0; j < 4; ++j) acc[i][j] = 0.f;

#pragma unroll
        for (int d4 = 0; d4 < 16; ++d4) {
            float4 q4[4];
#pragma unroll
            for (int i = 0; i < 4; ++i)
                q4[i] = *(const float4*)&sQ[((qg << 2) + i) * AQ_STRIDE + (d4 << 2)];
#pragma unroll
            for (int j = 0; j < 4; ++j) {
                const int e = kt + (j << 4);
                float4 k4 = *(const float4*)&sKV[(e << 6) + (((d4 + e) & 15) << 2)];
#pragma unroll
                for (int i = 0; i < 4; ++i) {
                    acc[i][j] = fmaf(q4[i].x, k4.x, acc[i][j]);
                    acc[i][j] = fmaf(q4[i].y, k4.y, acc[i][j]);
                    acc[i][j] = fmaf(q4[i].z, k4.z, acc[i][j]);
                    acc[i][j] = fmaf(q4[i].w, k4.w, acc[i][j]);
                }
            }
        }
#pragma unroll
        for (int j = 0; j < 4; ++j) {
            const int kglob = (c4 << 6) + kt + (j << 4);
            float4 v;
            v.x = acc[0][j]; v.y = acc[1][j]; v.z = acc[2][j]; v.w = acc[3][j];
            *(float4*)&sPT[kglob * APT_STRIDE + (qg << 2)] = v;
        }
#endif
    }
    __syncthreads();

    {
        const int row = tid >> 2;
        const int part = tid & 3;
        const int kbeg = part << 6;

        const int4* mrow = (const int4*)(pre_mask + ((size_t)bs * NQ + row) * NE + kbeg);
        uint64_t bits = 0;
#pragma unroll
        for (int g = 0; g < 16; ++g) {
            int4 m = mrow[g];
            uint64_t b = (uint64_t)(m.x != 0) | ((uint64_t)(m.y != 0) << 1) |
                         ((uint64_t)(m.z != 0) << 2) | ((uint64_t)(m.w != 0) << 3);
            bits |= b << (g << 2);
        }

        float mx = NEG_INF;
#pragma unroll 8
        for (int k = 0; k < 64; ++k) {
            if (!((bits >> k) & 1ull))
                mx = fmaxf(mx, sPT[(kbeg + k) * APT_STRIDE + row]);
        }
        sRed[(row << 2) + part] = mx;
        __syncthreads();
        const float rm = fmaxf(fmaxf(sRed[row << 2], sRed[(row << 2) + 1]),
                               fmaxf(sRed[(row << 2) + 2], sRed[(row << 2) + 3]));
        __syncthreads();

        const bool live = (rm != NEG_INF);
        float ssum = 0.f;
#pragma unroll 8
        for (int k = 0; k < 64; ++k) {
            float* p = &sPT[(kbeg + k) * APT_STRIDE + row];
            float e = 0.f;
            if (live && !((bits >> k) & 1ull)) e = __expf(*p - rm);
            *p = e;
            ssum += e;
        }
        sRed[(row << 2) + part] = ssum;
        __syncthreads();
        if (tid < 64) {
            const float t = sRed[tid << 2] + sRed[(tid << 2) + 1] +
                            sRed[(tid << 2) + 2] + sRed[(tid << 2) + 3];
            sInv[tid] = (t > 0.f) ? (1.f / t) : 0.f;
        }
    }

    const int qg2 = tid & 15;
    const int dg = tid >> 4;

#if HAS_TCGEN05
    unsigned long long accp2[4][2];
#pragma unroll
    for (int i = 0; i < 4; ++i) { accp2[i][0] = 0ull; accp2[i][1] = 0ull; }
#else
    float acc2[4][4];
#pragma unroll
    for (int i = 0; i < 4; ++i)
#pragma unroll
        for (int l = 0; l < 4; ++l) acc2[i][l] = 0.f;
#endif

    for (int c4 = 0; c4 < 4; ++c4) {
        __syncthreads();
        load_chunk(KV + ((size_t)bs * NE + (c4 << 6)) * (2 * EMBED_DIM) + EMBED_DIM + h * HEAD_DIM);
        __syncthreads();

#if HAS_TCGEN05
#pragma unroll 4
        for (int e = 0; e < 64; ++e) {
            const int kglob = (c4 << 6) + e;
            float4 w4 = *(const float4*)&sPT[kglob * APT_STRIDE + (qg2 << 2)];
            ulonglong2 v2 = *(const ulonglong2*)&sKV[(e << 6) + ((((dg) + e) & 15) << 2)];
            unsigned long long w0 = dup2(w4.x);
            unsigned long long w1 = dup2(w4.y);
            unsigned long long w2 = dup2(w4.z);
            unsigned long long w3 = dup2(w4.w);
            fma2(accp2[0][0], w0, v2.x);
            fma2(accp2[0][1], w0, v2.y);
            fma2(accp2[1][0], w1, v2.x);
            fma2(accp2[1][1], w1, v2.y);
            fma2(accp2[2][0], w2, v2.x);
            fma2(accp2[2][1], w2, v2.y);
            fma2(accp2[3][0], w3, v2.x);
            fma2(accp2[3][1], w3, v2.y);
        }
#else
#pragma unroll 4
        for (int e = 0; e < 64; ++e) {
            const int kglob = (c4 << 6) + e;
            float4 w4 = *(const float4*)&sPT[kglob * APT_STRIDE + (qg2 << 2)];
            float4 v4 = *(const float4*)&sKV[(e << 6) + ((((dg) + e) & 15) << 2)];
            acc2[0][0] = fmaf(w4.x, v4.x, acc2[0][0]);
            acc2[0][1] = fmaf(w4.x, v4.y, acc2[0][1]);
            acc2[0][2] = fmaf(w4.x, v4.z, acc2[0][2]);
            acc2[0][3] = fmaf(w4.x, v4.w, acc2[0][3]);
            acc2[1][0] = fmaf(w4.y, v4.x, acc2[1][0]);
            acc2[1][1] = fmaf(w4.y, v4.y, acc2[1][1]);
            acc2[1][2] = fmaf(w4.y, v4.z, acc2[1][2]);
            acc2[1][3] = fmaf(w4.y, v4.w, acc2[1][3]);
            acc2[2][0] = fmaf(w4.z, v4.x, acc2[2][0]);
            acc2[2][1] = fmaf(w4.z, v4.y, acc2[2][1]);
            acc2[2][2] = fmaf(w4.z, v4.z, acc2[2][2]);
            acc2[2][3] = fmaf(w4.z, v4.w, acc2[2][3]);
            acc2[3][0] = fmaf(w4.w, v4.x, acc2[3][0]);
            acc2[3][1] = fmaf(w4.w, v4.y, acc2[3][1]);
            acc2[3][2] = fmaf(w4.w, v4.z, acc2[3][2]);
            acc2[3][3] = fmaf(w4.w, v4.w, acc2[3][3]);
        }
#endif
    }

    const int k0 = h * HEAD_DIM + ((dg >> 1) << 3);
    const int sub = (dg & 1) << 3;
#pragma unroll
    for (int i = 0; i < 4; ++i) {
        const int qi = (qg2 << 2) + i;
        const float inv = sInv[qi];
        float x[4];
#if HAS_TCGEN05
        x[0] = lo32(accp2[i][0]) * inv;
        x[1] = hi32(accp2[i][0]) * inv;
        x[2] = lo32(accp2[i][1]) * inv;
        x[3] = hi32(accp2[i][1]) * inv;
#else
#pragma unroll
        for (int j = 0; j < 4; ++j) x[j] = acc2[i][j] * inv;
#endif
        uint2 hv;
        pack4h(x, hv);
        const int m = bs * NQ + qi;
        const size_t o = tiled_off(m, k0) + sub;
        *(uint2*)((char*)Ah + o) = hv;
    }
}

// ---------------------------------------------------------------------------
// kernel_launch
// ---------------------------------------------------------------------------
extern "C" void kernel_launch(void* const* d_in, const int* in_sizes, int n_in,
                              void* d_out, int out_size)
{
    const float* entities  = (const float*)d_in[0];
    const int*   pre_mask  = (const int*)d_in[1];
    const int*   post_mask = (const int*)d_in[2];
    const float* W_in      = (const float*)d_in[3];
    const float* W_out     = (const float*)d_in[4];
    const float* b_out     = (const float*)d_in[5];
    float* out = (float*)d_out;

    float *Qs, *KVs;
    __half *eh, *qh, *ah, *wih, *woh;
    cudaGetSymbolAddress((void**)&Qs, g_Q);
    cudaGetSymbolAddress((void**)&KVs, g_KV);
    cudaGetSymbolAddress((void**)&eh, g_ent_h);
    cudaGetSymbolAddress((void**)&qh, g_q_h);
    cudaGetSymbolAddress((void**)&ah, g_attn_h);
    cudaGetSymbolAddress((void**)&wih, g_WinT_h);
    cudaGetSymbolAddress((void**)&woh, g_WoutT_h);

    cudaFuncSetAttribute(gemm_fp16<false>,
                         cudaFuncAttributeMaxDynamicSharedMemorySize, GEMM_DYN_SMEM);
    cudaFuncSetAttribute(gemm_fp16<true>,
                         cudaFuncAttributeMaxDynamicSharedMemorySize, GEMM_DYN_SMEM);
    cudaFuncSetAttribute(attn_kernel,
                         cudaFuncAttributeMaxDynamicSharedMemorySize, ATTN_SMEM_BYTES);

    // 1) split entities -> tiled fp16 (+ compact Q rows)
    {
        int units = (BS * NE) << 6;
        split_tiledA<<<(units + 255) / 256, 256>>>(entities, eh, qh, BS * NE, 1);
    }
    // 2) split+transpose weights -> tiled fp16
    {
        int u1 = QKV_DIM << 6;
        splitT_tiled<<<(u1 + 255) / 256, 256>>>(W_in, wih, QKV_DIM);
        int u2 = OUT_DIM << 6;
        splitT_tiled<<<(u2 + 255) / 256, 256>>>(W_out, woh, OUT_DIM);
    }
    // 3) Q = q_ent @ W_in[:, 0:512]     M=32768, N=512
    gemm_fp16<false><<<dim3(EMBED_DIM / 128, (BS * NQ) / 128), 256, GEMM_DYN_SMEM>>>(
        qh, wih, Qs, EMBED_DIM, nullptr, nullptr);

    // 4) KV = entities @ W_in[:, 512:1536]  (B panels 4..11: +4*8*8192 elems)
    gemm_fp16<false><<<dim3((2 * EMBED_DIM) / 128, (BS * NE) / 128), 256, GEMM_DYN_SMEM>>>(
        eh, wih + 262144, KVs, 2 * EMBED_DIM, nullptr, nullptr);

    // 5) attention (writes tiled fp16 directly)
    attn_kernel<<<dim3(N_HEADS, BS), 256, ATTN_SMEM_BYTES>>>(Qs, KVs, pre_mask, ah);

    // 6) out = ATTN @ W_out + b_out, post-masked   M=32768, N=512
    gemm_fp16<true><<<dim3(OUT_DIM / 128, (BS * NQ) / 128), 256, GEMM_DYN_SMEM>>>(
        ah, woh, out, OUT_DIM, b_out, post_mask);
}

// round 13
// speedup vs baseline: 1.3157x; 1.0123x over previous
#include <cuda_runtime.h>
#include <cuda_bf16.h>
#include <cuda_fp16.h>
#include <math.h>
#include <stdint.h>

// Problem constants
#define BS 512
#define NE 256
#define NQ 64
#define IN_DIM 512
#define EMBED_DIM 512
#define OUT_DIM 512
#define N_HEADS 8
#define HEAD_DIM 64
#define QKV_DIM (3 * EMBED_DIM)

// Arch-feature gate: tcgen05 / f32x2 only exist in arch-specific passes.
#if defined(__CUDA_ARCH__) && (defined(__CUDA_ARCH_FEAT_SM103_ALL) || defined(__CUDA_ARCH_FEAT_SM100_ALL) || defined(__CUDA_ARCH_FEAT_SM101_ALL))
#define HAS_TCGEN05 1
#else
#define HAS_TCGEN05 0
#endif

// ---------------------------------------------------------------------------
// Scratch (device globals). GEMM operands live in TILE-CONTIGUOUS,
// PRE-SWIZZLED (SW128) layout: [M/128 panels][8 K-chunks][16384 bytes], fp16.
// Q/KV intermediates are now fp16 too (row-major).
// ---------------------------------------------------------------------------
__device__ __half g_Q[(size_t)BS * NQ * EMBED_DIM];
__device__ __half g_KV[(size_t)BS * NE * (2 * EMBED_DIM)];
__device__ __align__(1024) __half g_ent_h[(size_t)BS * NE * IN_DIM];
__device__ __align__(1024) __half g_q_h[(size_t)BS * NQ * IN_DIM];
__device__ __align__(1024) __half g_attn_h[(size_t)BS * NQ * EMBED_DIM];
__device__ __align__(1024) __half g_WinT_h[(size_t)QKV_DIM * IN_DIM];
__device__ __align__(1024) __half g_WoutT_h[(size_t)OUT_DIM * EMBED_DIM];

// ---------------------------------------------------------------------------
// Common helpers
// ---------------------------------------------------------------------------
__device__ __forceinline__ uint32_t smem_u32(const void* p) {
    uint32_t a;
    asm("{ .reg .u64 t; cvta.to.shared.u64 t, %1; cvt.u32.u64 %0, t; }" : "=r"(a) : "l"(p));
    return a;
}
__device__ __forceinline__ void cp16(uint32_t s, const void* g) {
    asm volatile("cp.async.cg.shared.global [%0], [%1], 16;" :: "r"(s), "l"(g) : "memory");
}
__device__ __forceinline__ void ldsm4(uint32_t* r, uint32_t addr) {
    asm volatile("ldmatrix.sync.aligned.m8n8.x4.shared.b16 {%0,%1,%2,%3}, [%4];"
                 : "=r"(r[0]), "=r"(r[1]), "=r"(r[2]), "=r"(r[3]) : "r"(addr));
}
__device__ __forceinline__ void mma_fp16(float* d, const uint32_t* a, const uint32_t* b) {
    asm volatile("mma.sync.aligned.m16n8k16.row.col.f32.f16.f16.f32 "
                 "{%0,%1,%2,%3}, {%4,%5,%6,%7}, {%8,%9}, {%0,%1,%2,%3};"
                 : "+f"(d[0]), "+f"(d[1]), "+f"(d[2]), "+f"(d[3])
                 : "r"(a[0]), "r"(a[1]), "r"(a[2]), "r"(a[3]), "r"(b[0]), "r"(b[1]));
}

// fp32[8] -> fp16 packed 16B unit
__device__ __forceinline__ void pack8h(const float* src, uint4& hv) {
    uint32_t* hp = (uint32_t*)&hv;
#pragma unroll
    for (int j = 0; j < 4; ++j) {
        __half2 h2;
        h2.x = __float2half(src[2 * j]);
        h2.y = __float2half(src[2 * j + 1]);
        hp[j] = *(uint32_t*)&h2;
    }
}
// fp32[4] -> fp16 packed 8B unit
__device__ __forceinline__ void pack4h(const float* src, uint2& hv) {
    uint32_t* hp = (uint32_t*)&hv;
#pragma unroll
    for (int j = 0; j < 2; ++j) {
        __half2 h2;
        h2.x = __float2half(src[2 * j]);
        h2.y = __float2half(src[2 * j + 1]);
        hp[j] = *(uint32_t*)&h2;
    }
}
// fp16x4 (uint2) -> float4
__device__ __forceinline__ float4 h4_to_f4(uint2 r) {
    __half2 a = *(__half2*)&r.x;
    __half2 b = *(__half2*)&r.y;
    float2 fa = __half22float2(a);
    float2 fb = __half22float2(b);
    float4 o;
    o.x = fa.x; o.y = fa.y; o.z = fb.x; o.w = fb.y;
    return o;
}

// byte offset of (m, k) in tiled+swizzled layout (k multiple of 8)
__device__ __forceinline__ size_t tiled_off(int m, int k) {
    const int panel = m >> 7, r = m & 127, ch = k >> 6;
    uint32_t off = (uint32_t)(r << 7) + ((k & 63) << 1);
    off = off ^ ((off >> 3) & 0x70);
    return ((size_t)(panel * 8 + ch) << 14) + off;
}

#if HAS_TCGEN05
// ---------------------------------------------------------------------------
// tcgen05 + bulk-async + f32x2 helpers (arch-specific pass only)
// ---------------------------------------------------------------------------
__device__ __forceinline__ uint32_t elect_one_pred() {
    uint32_t p;
    asm volatile("{\n\t.reg .pred p;\n\telect.sync _|p, 0xFFFFFFFF;\n\tselp.b32 %0, 1, 0, p;\n\t}" : "=r"(p));
    return p;
}
#define TCGEN05_ALLOC(sa, n) \
    asm volatile("tcgen05.alloc.cta_group::1.sync.aligned.shared::cta.b32 [%0], %1;" :: "r"((uint32_t)(sa)), "r"((uint32_t)(n)) : "memory")
#define TCGEN05_DEALLOC(t, n) \
    asm volatile("tcgen05.dealloc.cta_group::1.sync.aligned.b32 %0, %1;" :: "r"(t), "r"((uint32_t)(n)))
#define TCGEN05_RELINQ() \
    asm volatile("tcgen05.relinquish_alloc_permit.cta_group::1.sync.aligned;")
#define TCGEN05_COMMIT(mb) \
    asm volatile("tcgen05.commit.cta_group::1.mbarrier::arrive::one.shared::cluster.b64 [%0];" :: "r"((uint32_t)(mb)) : "memory")
#define TCGEN05_FENCE_AFTER() asm volatile("tcgen05.fence::after_thread_sync;" ::: "memory")
#define TCGEN05_FENCE_BEFORE() asm volatile("tcgen05.fence::before_thread_sync;" ::: "memory")
#define TCGEN05_WAIT_LD() asm volatile("tcgen05.wait::ld.sync.aligned;" ::: "memory")
#define MBARRIER_INIT(mb, cnt) \
    asm volatile("mbarrier.init.shared.b64 [%0], %1;" :: "r"((uint32_t)(mb)), "r"((uint32_t)(cnt)) : "memory")
#define MBARRIER_INVAL(mb) \
    asm volatile("mbarrier.inval.shared.b64 [%0];" :: "r"((uint32_t)(mb)) : "memory")
#define MBARRIER_EXPECT_TX(mb, tx) \
    asm volatile("mbarrier.arrive.expect_tx.shared.b64 _, [%0], %1;" :: "r"((uint32_t)(mb)), "r"((uint32_t)(tx)) : "memory")
#define MBARRIER_WAIT_PARITY(mb, par) do {                                           \
    uint32_t _mb = (uint32_t)(mb); uint32_t _p = (uint32_t)(par); uint32_t _d;       \
    asm volatile("{\n\t.reg .pred p;\n\t"                                            \
        "mbarrier.try_wait.parity.acquire.cta.shared::cta.b64 p, [%1], %2;\n\t"      \
        "selp.b32 %0, 1, 0, p;\n\t}" : "=r"(_d) : "r"(_mb), "r"(_p) : "memory");     \
    if (!_d) {                                                                       \
        asm volatile("{\n\t.reg .pred P1;\n\t"                                       \
            "WL_%=:\n\t"                                                             \
            "mbarrier.try_wait.parity.acquire.cta.shared::cta.b64 P1, [%0], %1, 0x989680;\n\t" \
            "@P1 bra.uni WD_%=;\n\t"                                                 \
            "bra.uni WL_%=;\n\t"                                                     \
            "WD_%=:\n\t}" :: "r"(_mb), "r"(_p) : "memory");                          \
    }                                                                                \
} while (0)

__device__ __forceinline__ void cp_bulk(uint32_t dst, const void* src, uint32_t bytes, uint32_t mb) {
    asm volatile("cp.async.bulk.shared::cta.global.mbarrier::complete_tx::bytes [%0], [%1], %2, [%3];"
                 :: "r"(dst), "l"(src), "r"(bytes), "r"(mb) : "memory");
}

#define TCGEN05_LD_32X32B_X32(r, ta) \
    asm volatile( \
        "tcgen05.ld.sync.aligned.32x32b.x32.b32 " \
        "{%0, %1, %2, %3, %4, %5, %6, %7, " \
        " %8, %9, %10, %11, %12, %13, %14, %15, " \
        " %16, %17, %18, %19, %20, %21, %22, %23, " \
        " %24, %25, %26, %27, %28, %29, %30, %31}, [%32];" \
        : "=r"((r)[0]),  "=r"((r)[1]),  "=r"((r)[2]),  "=r"((r)[3]), \
          "=r"((r)[4]),  "=r"((r)[5]),  "=r"((r)[6]),  "=r"((r)[7]), \
          "=r"((r)[8]),  "=r"((r)[9]),  "=r"((r)[10]), "=r"((r)[11]), \
          "=r"((r)[12]), "=r"((r)[13]), "=r"((r)[14]), "=r"((r)[15]), \
          "=r"((r)[16]), "=r"((r)[17]), "=r"((r)[18]), "=r"((r)[19]), \
          "=r"((r)[20]), "=r"((r)[21]), "=r"((r)[22]), "=r"((r)[23]), \
          "=r"((r)[24]), "=r"((r)[25]), "=r"((r)[26]), "=r"((r)[27]), \
          "=r"((r)[28]), "=r"((r)[29]), "=r"((r)[30]), "=r"((r)[31]) \
        : "r"(ta))

static constexpr uint64_t SMEM_DESC_BASE_SW128 =
    (uint64_t(2) << 61) | (uint64_t(1) << 46) | (uint64_t(64) << 32) | (uint64_t(1) << 16);
#define MAKE_SMEM_DESC(ba) (SMEM_DESC_BASE_SW128 | ((uint64_t)((ba) >> 4) & 0x3FFF))

// Proven operand binding: %3 = idesc, %4 = enable, %5 = zero reg.
__device__ __forceinline__ void mma_f16_ss(uint32_t d, uint64_t da, uint64_t db,
                                           uint32_t idesc, bool en) {
    uint32_t e = en ? 1u : 0u;
    asm volatile(
        "{\n\t.reg .pred p;\n\t"
        "setp.ne.u32 p, %4, 0;\n\t"
        "tcgen05.mma.cta_group::1.kind::f16 [%0], %1, %2, %3, {%5, %5, %5, %5}, p;\n\t"
        "}"
        :: "r"(d), "l"(da), "l"(db), "r"(idesc), "r"(e), "r"(0u)
        : "memory");
}
// idesc: f32 accum, FP16 a (0), FP16 b (0), N=128, M=128
static constexpr uint32_t MMA_IDESC =
    (1u << 4) | ((128u / 8) << 17) | ((128u / 16) << 24);

// packed fp32x2 FMA (FFMA2)
__device__ __forceinline__ void fma2(unsigned long long& d,
                                     unsigned long long a, unsigned long long b) {
    asm("fma.rn.f32x2 %0, %1, %2, %0;" : "+l"(d) : "l"(a), "l"(b));
}
__device__ __forceinline__ unsigned long long dup2(float w) {
    unsigned long long r;
    asm("mov.b64 %0, {%1, %1};" : "=l"(r) : "r"(__float_as_uint(w)));
    return r;
}
__device__ __forceinline__ float lo32(unsigned long long a) {
    return __uint_as_float((uint32_t)a);
}
__device__ __forceinline__ float hi32(unsigned long long a) {
    return __uint_as_float((uint32_t)(a >> 32));
}
#endif // HAS_TCGEN05

#define GK 512
#define NCHUNKS 8
#define TILE_BYTES 16384

// ---------------------------------------------------------------------------
// fp16 GEMM: 128x128 tile, 3-stage pipeline (Round-12 proven).
// OUTH: write C as fp16 (QKV intermediates); else fp32 with bias/mask epilogue.
// ---------------------------------------------------------------------------
#define STAGE_BYTES (2 * TILE_BYTES)
#define NSTAGES 3
#define GEMM_DYN_SMEM (NSTAGES * STAGE_BYTES + 1024)

template <bool EPI, bool OUTH>
__global__ void __launch_bounds__(256)
gemm_fp16(const __half* __restrict__ A, const __half* __restrict__ B,
          void* __restrict__ Cv, int ldc,
          const float* __restrict__ bias, const int* __restrict__ post_mask)
{
    extern __shared__ char dyn_smem[];
    const int tid = threadIdx.x;
    const int wid = tid >> 5;
    const int lane = tid & 31;
    const int m0 = blockIdx.y << 7;
    const int n0 = blockIdx.x << 7;
    const int pm = blockIdx.y;
    const int pn = blockIdx.x;

    const uint32_t sbase = (smem_u32(dyn_smem) + 1023u) & ~1023u;

#if HAS_TCGEN05
    __shared__ uint32_t s_tmem_ptr[2];
    __shared__ __align__(8) uint64_t s_full[NSTAGES];
    __shared__ __align__(8) uint64_t s_empty[NSTAGES];
    __shared__ __align__(8) uint64_t s_done;

    if (wid == 0) {
        TCGEN05_ALLOC(smem_u32(s_tmem_ptr), 128);
        TCGEN05_RELINQ();
    }
    if (tid == 0) {
#pragma unroll
        for (int j = 0; j < NSTAGES; ++j) {
            MBARRIER_INIT(smem_u32(&s_full[j]), 1);
            MBARRIER_INIT(smem_u32(&s_empty[j]), 1);
        }
        MBARRIER_INIT(smem_u32(&s_done), 1);
    }
    __syncthreads();

    uint32_t tmem_base;
    asm volatile("ld.shared.b32 %0, [%1];" : "=r"(tmem_base) : "r"(smem_u32(s_tmem_ptr)));

    if (wid == 0 && elect_one_pred()) {
        uint32_t fa[NSTAGES], ea[NSTAGES];
#pragma unroll
        for (int j = 0; j < NSTAGES; ++j) {
            fa[j] = smem_u32(&s_full[j]);
            ea[j] = smem_u32(&s_empty[j]);
        }
        const char* pA = (const char*)A + (size_t)pm * (8 * TILE_BYTES);
        const char* pB = (const char*)B + (size_t)pn * (8 * TILE_BYTES);

        auto load_chunk = [&](int ch, int st) {
            const uint32_t sb = sbase + st * STAGE_BYTES;
            const uint32_t mb = fa[st];
            MBARRIER_EXPECT_TX(mb, STAGE_BYTES);
            const size_t o = (size_t)ch * TILE_BYTES;
            cp_bulk(sb,              pA + o, TILE_BYTES, mb);
            cp_bulk(sb + TILE_BYTES, pB + o, TILE_BYTES, mb);
        };

        load_chunk(0, 0);
        load_chunk(1, 1);
        load_chunk(2, 2);

        int fph[NSTAGES] = {0, 0, 0};
        int eph[NSTAGES] = {0, 0, 0};

        for (int c = 0; c < NCHUNKS; ++c) {
            const int st = c % NSTAGES;
            MBARRIER_WAIT_PARITY(fa[st], fph[st]);
            fph[st] ^= 1;

            const uint32_t sb = sbase + st * STAGE_BYTES;
            const uint64_t dA = MAKE_SMEM_DESC(sb);
            const uint64_t dB = MAKE_SMEM_DESC(sb + TILE_BYTES);
#pragma unroll
            for (int s = 0; s < 4; ++s) {
                const bool first = (c == 0) && (s == 0);
                mma_f16_ss(tmem_base, dA + 2 * s, dB + 2 * s, MMA_IDESC, !first);
            }
            if (c + NSTAGES < NCHUNKS) {
                TCGEN05_COMMIT(ea[st]);
                MBARRIER_WAIT_PARITY(ea[st], eph[st]);
                eph[st] ^= 1;
                load_chunk(c + NSTAGES, st);
            } else if (c == NCHUNKS - 1) {
                TCGEN05_COMMIT(smem_u32(&s_done));
            }
        }
    }

    MBARRIER_WAIT_PARITY(smem_u32(&s_done), 0);
    TCGEN05_FENCE_AFTER();

    // epilogue: warp (wid&3) -> 32-row subpartition, (wid>>2) -> column half
    {
        const int rsub = (wid & 3) << 5;
        const int colh = (wid >> 2) << 6;
        const int m = m0 + rsub + lane;
        bool zero = false;
        if (EPI) zero = (post_mask[m] != 0);

#pragma unroll
        for (int half = 0; half < 2; ++half) {
            const int cbase = colh + half * 32;
            uint32_t r[32];
            TCGEN05_LD_32X32B_X32(r, tmem_base + cbase);
            TCGEN05_WAIT_LD();
#pragma unroll
            for (int j = 0; j < 32; j += 4) {
                float v[4];
                v[0] = __uint_as_float(r[j + 0]);
                v[1] = __uint_as_float(r[j + 1]);
                v[2] = __uint_as_float(r[j + 2]);
                v[3] = __uint_as_float(r[j + 3]);
                if (EPI) {
                    const int n = n0 + cbase + j;
                    v[0] += bias[n + 0];
                    v[1] += bias[n + 1];
                    v[2] += bias[n + 2];
                    v[3] += bias[n + 3];
                    if (zero) { v[0] = 0.f; v[1] = 0.f; v[2] = 0.f; v[3] = 0.f; }
                }
                if (OUTH) {
                    __half* crow = (__half*)Cv + (size_t)m * ldc + n0;
                    uint2 hv;
                    pack4h(v, hv);
                    *(uint2*)(crow + cbase + j) = hv;
                } else {
                    float* crow = (float*)Cv + (size_t)m * ldc + n0;
                    float4 fv;
                    fv.x = v[0]; fv.y = v[1]; fv.z = v[2]; fv.w = v[3];
                    *(float4*)(crow + cbase + j) = fv;
                }
            }
        }
        TCGEN05_FENCE_BEFORE();
    }

    __syncthreads();
    if (tid == 0) {
#pragma unroll
        for (int j = 0; j < NSTAGES; ++j) {
            MBARRIER_INVAL(smem_u32(&s_full[j]));
            MBARRIER_INVAL(smem_u32(&s_empty[j]));
        }
        MBARRIER_INVAL(smem_u32(&s_done));
    }
    __syncthreads();
    if (wid == 0) TCGEN05_DEALLOC(tmem_base, 128);

#else
    // =========================== mma.sync fallback ==========================
    const int wm = (wid & 1) << 6;
    const int wn = (wid >> 1) << 5;

    auto issue_loads = [&](int ch, int st) {
        const uint32_t sb = sbase + st * STAGE_BYTES;
        const char* pA = (const char*)A + ((size_t)pm * 8 + ch) * TILE_BYTES;
        const char* pB = (const char*)B + ((size_t)pn * 8 + ch) * TILE_BYTES;
#pragma unroll
        for (int i = 0; i < 4; ++i) {
            const uint32_t u = (tid + (i << 8)) << 4;
            cp16(sb + u, pA + u);
            cp16(sb + TILE_BYTES + u, pB + u);
        }
        asm volatile("cp.async.commit_group;" ::: "memory");
    };

    float acc[4][4][4];
#pragma unroll
    for (int a = 0; a < 4; ++a)
#pragma unroll
        for (int b = 0; b < 4; ++b)
#pragma unroll
            for (int d = 0; d < 4; ++d) acc[a][b][d] = 0.f;

    issue_loads(0, 0);
    issue_loads(1, 1);

    for (int c = 0; c < NCHUNKS; ++c) {
        if (c < NCHUNKS - 1) asm volatile("cp.async.wait_group 1;" ::: "memory");
        else                 asm volatile("cp.async.wait_group 0;" ::: "memory");
        __syncthreads();
        const uint32_t sb = sbase + (c & 1) * STAGE_BYTES;

#pragma unroll
        for (int ks = 0; ks < 4; ++ks) {
            uint32_t av[4][4];
#pragma unroll
            for (int mf = 0; mf < 4; ++mf) {
                const uint32_t row = wm + (mf << 4) + (lane & 15);
                const uint32_t kp = (ks << 1) + (lane >> 4);
                const uint32_t off = (row << 7) + (kp << 4);
                const uint32_t sw = off ^ ((off >> 3) & 0x70);
                ldsm4(av[mf], sb + sw);
            }
            uint32_t bv[4][2];
#pragma unroll
            for (int nb = 0; nb < 2; ++nb) {
                const uint32_t row = wn + (nb << 4) + ((lane >> 4) << 3) + (lane & 7);
                const uint32_t kp = (ks << 1) + ((lane >> 3) & 1);
                const uint32_t off = (row << 7) + (kp << 4);
                const uint32_t sw = off ^ ((off >> 3) & 0x70);
                uint32_t t[4];
                ldsm4(t, sb + TILE_BYTES + sw);
                bv[2 * nb][0] = t[0]; bv[2 * nb][1] = t[1];
                bv[2 * nb + 1][0] = t[2]; bv[2 * nb + 1][1] = t[3];
            }
#pragma unroll
            for (int mf = 0; mf < 4; ++mf)
#pragma unroll
                for (int nf = 0; nf < 4; ++nf)
                    mma_fp16(acc[mf][nf], av[mf], bv[nf]);
        }
        __syncthreads();
        if (c + 2 < NCHUNKS) issue_loads(c + 2, (c + 2) & 1);
    }

#pragma unroll
    for (int mf = 0; mf < 4; ++mf) {
#pragma unroll
        for (int half = 0; half < 2; ++half) {
            const int m = m0 + wm + (mf << 4) + (half << 3) + (lane >> 2);
            bool zero = false;
            if (EPI) zero = (post_mask[m] != 0);
#pragma unroll
            for (int nf = 0; nf < 4; ++nf) {
                const int col = n0 + wn + (nf << 3) + ((lane & 3) << 1);
                float v0 = acc[mf][nf][half * 2 + 0];
                float v1 = acc[mf][nf][half * 2 + 1];
                if (EPI) {
                    v0 += bias[col];
                    v1 += bias[col + 1];
                    if (zero) { v0 = 0.f; v1 = 0.f; }
                }
                if (OUTH) {
                    __half* crow = (__half*)Cv + (size_t)m * ldc;
                    __half2 h2;
                    h2.x = __float2half(v0);
                    h2.y = __float2half(v1);
                    *(__half2*)(crow + col) = h2;
                } else {
                    float* crow = (float*)Cv + (size_t)m * ldc;
                    crow[col] = v0;
                    crow[col + 1] = v1;
                }
            }
        }
    }
#endif
}

// ---------------------------------------------------------------------------
// Splits: fp32 -> fp16 into TILED+SWIZZLED layout.
// ---------------------------------------------------------------------------
__global__ void __launch_bounds__(256)
split_tiledA(const float* __restrict__ in, __half* __restrict__ hh,
             __half* __restrict__ qh, int Mtot, int withQ)
{
    int i = blockIdx.x * blockDim.x + threadIdx.x;
    const int units = Mtot << 6;
    if (i >= units) return;
    const int m = i >> 6;
    const int k = (i & 63) << 3;

    float x[8];
    const float* src = in + (size_t)m * GK + k;
#pragma unroll
    for (int j = 0; j < 8; ++j) x[j] = src[j];

    uint4 hv;
    pack8h(x, hv);

    const size_t o = tiled_off(m, k);
    *(uint4*)((char*)hh + o) = hv;

    if (withQ && (m & 255) < 64) {
        const int mq = ((m >> 8) << 6) + (m & 63);
        const size_t oq = tiled_off(mq, k);
        *(uint4*)((char*)qh + oq) = hv;
    }
}

__global__ void __launch_bounds__(256)
splitT_tiled(const float* __restrict__ in, __half* __restrict__ hT, int Nd)
{
    int i = blockIdx.x * blockDim.x + threadIdx.x;
    const int units = Nd << 6;
    if (i >= units) return;
    const int n = i >> 6;
    const int k = (i & 63) << 3;

    float x[8];
#pragma unroll
    for (int j = 0; j < 8; ++j) x[j] = in[(size_t)(k + j) * Nd + n];
    uint4 hv;
    pack8h(x, hv);

    const size_t o = tiled_off(n, k);
    *(uint4*)((char*)hT + o) = hv;
}

// ---------------------------------------------------------------------------
// Attention (Round-12 proven hot loops): fp16 Q/KV in gmem, converted to fp32
// smem; FFMA2 compute; direct tiled fp16 output.
// ---------------------------------------------------------------------------
#define AQ_STRIDE 68
#define APT_STRIDE 68
#define A_SQ 0
#define A_SKV (64 * AQ_STRIDE)
#define A_SPT (A_SKV + 64 * 64)
#define A_SRED (A_SPT + 256 * APT_STRIDE)
#define A_SINV (A_SRED + 256)
#define ATTN_SMEM_FLOATS (A_SINV + 64)
#define ATTN_SMEM_BYTES (ATTN_SMEM_FLOATS * 4)

__global__ void __launch_bounds__(256, 2)
attn_kernel(const __half* __restrict__ Q,
            const __half* __restrict__ KV,
            const int* __restrict__ pre_mask,
            __half* __restrict__ Ah)
{
    extern __shared__ float sm[];
    float* sQ  = sm + A_SQ;
    float* sKV = sm + A_SKV;
    float* sPT = sm + A_SPT;
    float* sRed = sm + A_SRED;
    float* sInv = sm + A_SINV;

    const int tid = threadIdx.x;
    const int h = blockIdx.x;
    const int bs = blockIdx.y;
    const float NEG_INF = -INFINITY;

    {
        const int lr = tid >> 4;
        const int lc = (tid & 15) << 2;
#pragma unroll
        for (int it = 0; it < 4; ++it) {
            const int qi = lr + (it << 4);
            uint2 raw = *(const uint2*)(Q + ((size_t)bs * NQ + qi) * EMBED_DIM + h * HEAD_DIM + lc);
            float4 v = h4_to_f4(raw);
            float* dst = &sQ[qi * AQ_STRIDE + lc];
            dst[0] = v.x * 0.125f;
            dst[1] = v.y * 0.125f;
            dst[2] = v.z * 0.125f;
            dst[3] = v.w * 0.125f;
        }
    }

    auto load_chunk = [&](const __half* base) {
#pragma unroll
        for (int it = 0; it < 4; ++it) {
            const int idx = tid + (it << 8);
            const int e = idx >> 4;
            const int c = idx & 15;
            uint2 raw = *(const uint2*)(base + (size_t)e * (2 * EMBED_DIM) + (c << 2));
            float4 v = h4_to_f4(raw);
            *(float4*)&sKV[(e << 6) + (((c + e) & 15) << 2)] = v;
        }
    };

    const int qg = tid >> 4;
    const int kt = tid & 15;

    for (int c4 = 0; c4 < 4; ++c4) {
        __syncthreads();
        load_chunk(KV + ((size_t)bs * NE + (c4 << 6)) * (2 * EMBED_DIM) + h * HEAD_DIM);
        __syncthreads();

#if HAS_TCGEN05
        unsigned long long accp[4][4];
#pragma unroll
        for (int i = 0; i < 4; ++i)
#pragma unroll
            for (int j = 0; j < 4; ++j) accp[i][j] = 0ull;

#pragma unroll
        for (int d4 = 0; d4 < 16; ++d4) {
            ulonglong2 q2[4];
#pragma unroll
            for (int i = 0; i < 4; ++i)
                q2[i] = *(const ulonglong2*)&sQ[((qg << 2) + i) * AQ_STRIDE + (d4 << 2)];
#pragma unroll
            for (int j = 0; j < 4; ++j) {
                const int e = kt + (j << 4);
                ulonglong2 k2 = *(const ulonglong2*)&sKV[(e << 6) + (((d4 + e) & 15) << 2)];
#pragma unroll
                for (int i = 0; i < 4; ++i) {
                    fma2(accp[i][j], q2[i].x, k2.x);
                    fma2(accp[i][j], q2[i].y, k2.y);
                }
            }
        }
#pragma unroll
        for (int j = 0; j < 4; ++j) {
            const int kglob = (c4 << 6) + kt + (j << 4);
            float4 v;
            v.x = lo32(accp[0][j]) + hi32(accp[0][j]);
            v.y = lo32(accp[1][j]) + hi32(accp[1][j]);
            v.z = lo32(accp[2][j]) + hi32(accp[2][j]);
            v.w = lo32(accp[3][j]) + hi32(accp[3][j]);
            *(float4*)&sPT[kglob * APT_STRIDE + (qg << 2)] = v;
        }
#else
        float acc[4][4];
#pragma unroll
        for (int i = 0; i < 4; ++i)
#pragma unroll
            for (int j = 0; j < 4; ++j) acc[i][j] = 0.f;

#pragma unroll
        for (int d4 = 0; d4 < 16; ++d4) {
            float4 q4[4];
#pragma unroll
            for (int i = 0; i < 4; ++i)
                q4[i] = *(const float4*)&sQ[((qg << 2) + i) * AQ_STRIDE + (d4 << 2)];
#pragma unroll
            for (int j = 0; j < 4; ++j) {
                const int e = kt + (j << 4);
                float4 k4 = *(const float4*)&sKV[(e << 6) + (((d4 + e) & 15) << 2)];
#pragma unroll
                for (int i = 0; i < 4; ++i) {
                    acc[i][j] = fmaf(q4[i].x, k4.x, acc[i][j]);
                    acc[i][j] = fmaf(q4[i].y, k4.y, acc[i][j]);
                    acc[i][j] = fmaf(q4[i].z, k4.z, acc[i][j]);
                    acc[i][j] = fmaf(q4[i].w, k4.w, acc[i][j]);
                }
            }
        }
#pragma unroll
        for (int j = 0; j < 4; ++j) {
            const int kglob = (c4 << 6) + kt + (j << 4);
            float4 v;
            v.x = acc[0][j]; v.y = acc[1][j]; v.z = acc[2][j]; v.w = acc[3][j];
            *(float4*)&sPT[kglob * APT_STRIDE + (qg << 2)] = v;
        }
#endif
    }
    __syncthreads();

    {
        const int row = tid >> 2;
        const int part = tid & 3;
        const int kbeg = part << 6;

        const int4* mrow = (const int4*)(pre_mask + ((size_t)bs * NQ + row) * NE + kbeg);
        uint64_t bits = 0;
#pragma unroll
        for (int g = 0; g < 16; ++g) {
            int4 m = mrow[g];
            uint64_t b = (uint64_t)(m.x != 0) | ((uint64_t)(m.y != 0) << 1) |
                         ((uint64_t)(m.z != 0) << 2) | ((uint64_t)(m.w != 0) << 3);
            bits |= b << (g << 2);
        }

        float mx = NEG_INF;
#pragma unroll 8
        for (int k = 0; k < 64; ++k) {
            if (!((bits >> k) & 1ull))
                mx = fmaxf(mx, sPT[(kbeg + k) * APT_STRIDE + row]);
        }
        sRed[(row << 2) + part] = mx;
        __syncthreads();
        const float rm = fmaxf(fmaxf(sRed[row << 2], sRed[(row << 2) + 1]),
                               fmaxf(sRed[(row << 2) + 2], sRed[(row << 2) + 3]));
        __syncthreads();

        const bool live = (rm != NEG_INF);
        float ssum = 0.f;
#pragma unroll 8
        for (int k = 0; k < 64; ++k) {
            float* p = &sPT[(kbeg + k) * APT_STRIDE + row];
            float e = 0.f;
            if (live && !((bits >> k) & 1ull)) e = __expf(*p - rm);
            *p = e;
            ssum += e;
        }
        sRed[(row << 2) + part] = ssum;
        __syncthreads();
        if (tid < 64) {
            const float t = sRed[tid << 2] + sRed[(tid << 2) + 1] +
                            sRed[(tid << 2) + 2] + sRed[(tid << 2) + 3];
            sInv[tid] = (t > 0.f) ? (1.f / t) : 0.f;
        }
    }

    const int qg2 = tid & 15;
    const int dg = tid >> 4;

#if HAS_TCGEN05
    unsigned long long accp2[4][2];
#pragma unroll
    for (int i = 0; i < 4; ++i) { accp2[i][0] = 0ull; accp2[i][1] = 0ull; }
#else
    float acc2[4][4];
#pragma unroll
    for (int i = 0; i < 4; ++i)
#pragma unroll
        for (int l = 0; l < 4; ++l) acc2[i][l] = 0.f;
#endif

    for (int c4 = 0; c4 < 4; ++c4) {
        __syncthreads();
        load_chunk(KV + ((size_t)bs * NE + (c4 << 6)) * (2 * EMBED_DIM) + EMBED_DIM + h * HEAD_DIM);
        __syncthreads();

#if HAS_TCGEN05
#pragma unroll 4
        for (int e = 0; e < 64; ++e) {
            const int kglob = (c4 << 6) + e;
            float4 w4 = *(const float4*)&sPT[kglob * APT_STRIDE + (qg2 << 2)];
            ulonglong2 v2 = *(const ulonglong2*)&sKV[(e << 6) + ((((dg) + e) & 15) << 2)];
            unsigned long long w0 = dup2(w4.x);
            unsigned long long w1 = dup2(w4.y);
            unsigned long long w2 = dup2(w4.z);
            unsigned long long w3 = dup2(w4.w);
            fma2(accp2[0][0], w0, v2.x);
            fma2(accp2[0][1], w0, v2.y);
            fma2(accp2[1][0], w1, v2.x);
            fma2(accp2[1][1], w1, v2.y);
            fma2(accp2[2][0], w2, v2.x);
            fma2(accp2[2][1], w2, v2.y);
            fma2(accp2[3][0], w3, v2.x);
            fma2(accp2[3][1], w3, v2.y);
        }
#else
#pragma unroll 4
        for (int e = 0; e < 64; ++e) {
            const int kglob = (c4 << 6) + e;
            float4 w4 = *(const float4*)&sPT[kglob * APT_STRIDE + (qg2 << 2)];
            float4 v4 = *(const float4*)&sKV[(e << 6) + ((((dg) + e) & 15) << 2)];
            acc2[0][0] = fmaf(w4.x, v4.x, acc2[0][0]);
            acc2[0][1] = fmaf(w4.x, v4.y, acc2[0][1]);
            acc2[0][2] = fmaf(w4.x, v4.z, acc2[0][2]);
            acc2[0][3] = fmaf(w4.x, v4.w, acc2[0][3]);
            acc2[1][0] = fmaf(w4.y, v4.x, acc2[1][0]);
            acc2[1][1] = fmaf(w4.y, v4.y, acc2[1][1]);
            acc2[1][2] = fmaf(w4.y, v4.z, acc2[1][2]);
            acc2[1][3] = fmaf(w4.y, v4.w, acc2[1][3]);
            acc2[2][0] = fmaf(w4.z, v4.x, acc2[2][0]);
            acc2[2][1] = fmaf(w4.z, v4.y, acc2[2][1]);
            acc2[2][2] = fmaf(w4.z, v4.z, acc2[2][2]);
            acc2[2][3] = fmaf(w4.z, v4.w, acc2[2][3]);
            acc2[3][0] = fmaf(w4.w, v4.x, acc2[3][0]);
            acc2[3][1] = fmaf(w4.w, v4.y, acc2[3][1]);
            acc2[3][2] = fmaf(w4.w, v4.z, acc2[3][2]);
            acc2[3][3] = fmaf(w4.w, v4.w, acc2[3][3]);
        }
#endif
    }

    const int k0 = h * HEAD_DIM + ((dg >> 1) << 3);
    const int sub = (dg & 1) << 3;
#pragma unroll
    for (int i = 0; i < 4; ++i) {
        const int qi = (qg2 << 2) + i;
        const float inv = sInv[qi];
        float x[4];
#if HAS_TCGEN05
        x[0] = lo32(accp2[i][0]) * inv;
        x[1] = hi32(accp2[i][0]) * inv;
        x[2] = lo32(accp2[i][1]) * inv;
        x[3] = hi32(accp2[i][1]) * inv;
#else
#pragma unroll
        for (int j = 0; j < 4; ++j) x[j] = acc2[i][j] * inv;
#endif
        uint2 hv;
        pack4h(x, hv);
        const int m = bs * NQ + qi;
        const size_t o = tiled_off(m, k0) + sub;
        *(uint2*)((char*)Ah + o) = hv;
    }
}

// ---------------------------------------------------------------------------
// kernel_launch
// ---------------------------------------------------------------------------
extern "C" void kernel_launch(void* const* d_in, const int* in_sizes, int n_in,
                              void* d_out, int out_size)
{
    const float* entities  = (const float*)d_in[0];
    const int*   pre_mask  = (const int*)d_in[1];
    const int*   post_mask = (const int*)d_in[2];
    const float* W_in      = (const float*)d_in[3];
    const float* W_out     = (const float*)d_in[4];
    const float* b_out     = (const float*)d_in[5];
    float* out = (float*)d_out;

    __half *Qs, *KVs;
    __half *eh, *qh, *ah, *wih, *woh;
    cudaGetSymbolAddress((void**)&Qs, g_Q);
    cudaGetSymbolAddress((void**)&KVs, g_KV);
    cudaGetSymbolAddress((void**)&eh, g_ent_h);
    cudaGetSymbolAddress((void**)&qh, g_q_h);
    cudaGetSymbolAddress((void**)&ah, g_attn_h);
    cudaGetSymbolAddress((void**)&wih, g_WinT_h);
    cudaGetSymbolAddress((void**)&woh, g_WoutT_h);

    cudaFuncSetAttribute((const void*)gemm_fp16<false, true>,
                         cudaFuncAttributeMaxDynamicSharedMemorySize, GEMM_DYN_SMEM);
    cudaFuncSetAttribute((const void*)gemm_fp16<true, false>,
                         cudaFuncAttributeMaxDynamicSharedMemorySize, GEMM_DYN_SMEM);
    cudaFuncSetAttribute(attn_kernel,
                         cudaFuncAttributeMaxDynamicSharedMemorySize, ATTN_SMEM_BYTES);

    // 1) split entities -> tiled fp16 (+ compact Q rows)
    {
        int units = (BS * NE) << 6;
        split_tiledA<<<(units + 255) / 256, 256>>>(entities, eh, qh, BS * NE, 1);
    }
    // 2) split+transpose weights -> tiled fp16
    {
        int u1 = QKV_DIM << 6;
        splitT_tiled<<<(u1 + 255) / 256, 256>>>(W_in, wih, QKV_DIM);
        int u2 = OUT_DIM << 6;
        splitT_tiled<<<(u2 + 255) / 256, 256>>>(W_out, woh, OUT_DIM);
    }
    // 3) Q = q_ent @ W_in[:, 0:512]     M=32768, N=512  (fp16 output)
    gemm_fp16<false, true><<<dim3(EMBED_DIM / 128, (BS * NQ) / 128), 256, GEMM_DYN_SMEM>>>(
        qh, wih, Qs, EMBED_DIM, nullptr, nullptr);

    // 4) KV = entities @ W_in[:, 512:1536]  (fp16 output)
    gemm_fp16<false, true><<<dim3((2 * EMBED_DIM) / 128, (BS * NE) / 128), 256, GEMM_DYN_SMEM>>>(
        eh, wih + 262144, KVs, 2 * EMBED_DIM, nullptr, nullptr);

    // 5) attention (fp16 in, writes tiled fp16 directly)
    attn_kernel<<<dim3(N_HEADS, BS), 256, ATTN_SMEM_BYTES>>>(Qs, KVs, pre_mask, ah);

    // 6) out = ATTN @ W_out + b_out, post-masked  (fp32 output)
    gemm_fp16<true, false><<<dim3(OUT_DIM / 128, (BS * NQ) / 128), 256, GEMM_DYN_SMEM>>>(
        ah, woh, out, OUT_DIM, b_out, post_mask);
}

// round 15
// speedup vs baseline: 2.0393x; 1.5499x over previous
#include <cuda_runtime.h>
#include <cuda_bf16.h>
#include <cuda_fp16.h>
#include <math.h>
#include <stdint.h>

// Problem constants
#define BS 512
#define NE 256
#define NQ 64
#define IN_DIM 512
#define EMBED_DIM 512
#define OUT_DIM 512
#define N_HEADS 8
#define HEAD_DIM 64
#define QKV_DIM (3 * EMBED_DIM)

// Arch-feature gate: tcgen05 only exists in arch-specific passes.
#if defined(__CUDA_ARCH__) && (defined(__CUDA_ARCH_FEAT_SM103_ALL) || defined(__CUDA_ARCH_FEAT_SM100_ALL) || defined(__CUDA_ARCH_FEAT_SM101_ALL))
#define HAS_TCGEN05 1
#else
#define HAS_TCGEN05 0
#endif

// ---------------------------------------------------------------------------
// Scratch (device globals). GEMM operands live in TILE-CONTIGUOUS,
// PRE-SWIZZLED (SW128) layout: [M/128 panels][8 K-chunks][16384 bytes], fp16.
// ---------------------------------------------------------------------------
__device__ __half g_Q[(size_t)BS * NQ * EMBED_DIM];
__device__ __half g_KV[(size_t)BS * NE * (2 * EMBED_DIM)];
__device__ __align__(1024) __half g_ent_h[(size_t)BS * NE * IN_DIM];
__device__ __align__(1024) __half g_q_h[(size_t)BS * NQ * IN_DIM];
__device__ __align__(1024) __half g_attn_h[(size_t)BS * NQ * EMBED_DIM];
__device__ __align__(1024) __half g_WinT_h[(size_t)QKV_DIM * IN_DIM];
__device__ __align__(1024) __half g_WoutT_h[(size_t)OUT_DIM * EMBED_DIM];

// ---------------------------------------------------------------------------
// Common helpers
// ---------------------------------------------------------------------------
__device__ __forceinline__ uint32_t smem_u32(const void* p) {
    uint32_t a;
    asm("{ .reg .u64 t; cvta.to.shared.u64 t, %1; cvt.u32.u64 %0, t; }" : "=r"(a) : "l"(p));
    return a;
}
__device__ __forceinline__ void cp16(uint32_t s, const void* g) {
    asm volatile("cp.async.cg.shared.global [%0], [%1], 16;" :: "r"(s), "l"(g) : "memory");
}
__device__ __forceinline__ void ldsm4(uint32_t* r, uint32_t addr) {
    asm volatile("ldmatrix.sync.aligned.m8n8.x4.shared.b16 {%0,%1,%2,%3}, [%4];"
                 : "=r"(r[0]), "=r"(r[1]), "=r"(r[2]), "=r"(r[3]) : "r"(addr));
}
__device__ __forceinline__ void ldsm4t(uint32_t* r, uint32_t addr) {
    asm volatile("ldmatrix.sync.aligned.m8n8.x4.trans.shared.b16 {%0,%1,%2,%3}, [%4];"
                 : "=r"(r[0]), "=r"(r[1]), "=r"(r[2]), "=r"(r[3]) : "r"(addr));
}
__device__ __forceinline__ void mma_fp16(float* d, const uint32_t* a, const uint32_t* b) {
    asm volatile("mma.sync.aligned.m16n8k16.row.col.f32.f16.f16.f32 "
                 "{%0,%1,%2,%3}, {%4,%5,%6,%7}, {%8,%9}, {%0,%1,%2,%3};"
                 : "+f"(d[0]), "+f"(d[1]), "+f"(d[2]), "+f"(d[3])
                 : "r"(a[0]), "r"(a[1]), "r"(a[2]), "r"(a[3]), "r"(b[0]), "r"(b[1]));
}

// fp32[8] -> fp16 packed 16B unit
__device__ __forceinline__ void pack8h(const float* src, uint4& hv) {
    uint32_t* hp = (uint32_t*)&hv;
#pragma unroll
    for (int j = 0; j < 4; ++j) {
        __half2 h2;
        h2.x = __float2half(src[2 * j]);
        h2.y = __float2half(src[2 * j + 1]);
        hp[j] = *(uint32_t*)&h2;
    }
}
// fp32[4] -> fp16 packed 8B unit
__device__ __forceinline__ void pack4h(const float* src, uint2& hv) {
    uint32_t* hp = (uint32_t*)&hv;
#pragma unroll
    for (int j = 0; j < 2; ++j) {
        __half2 h2;
        h2.x = __float2half(src[2 * j]);
        h2.y = __float2half(src[2 * j + 1]);
        hp[j] = *(uint32_t*)&h2;
    }
}

// byte offset of (m, k) in tiled+swizzled layout (k multiple of 8)
__device__ __forceinline__ size_t tiled_off(int m, int k) {
    const int panel = m >> 7, r = m & 127, ch = k >> 6;
    uint32_t off = (uint32_t)(r << 7) + ((k & 63) << 1);
    off = off ^ ((off >> 3) & 0x70);
    return ((size_t)(panel * 8 + ch) << 14) + off;
}

#if HAS_TCGEN05
// ---------------------------------------------------------------------------
// tcgen05 + bulk-async helpers (arch-specific pass only)
// ---------------------------------------------------------------------------
__device__ __forceinline__ uint32_t elect_one_pred() {
    uint32_t p;
    asm volatile("{\n\t.reg .pred p;\n\telect.sync _|p, 0xFFFFFFFF;\n\tselp.b32 %0, 1, 0, p;\n\t}" : "=r"(p));
    return p;
}
#define TCGEN05_ALLOC(sa, n) \
    asm volatile("tcgen05.alloc.cta_group::1.sync.aligned.shared::cta.b32 [%0], %1;" :: "r"((uint32_t)(sa)), "r"((uint32_t)(n)) : "memory")
#define TCGEN05_DEALLOC(t, n) \
    asm volatile("tcgen05.dealloc.cta_group::1.sync.aligned.b32 %0, %1;" :: "r"(t), "r"((uint32_t)(n)))
#define TCGEN05_RELINQ() \
    asm volatile("tcgen05.relinquish_alloc_permit.cta_group::1.sync.aligned;")
#define TCGEN05_COMMIT(mb) \
    asm volatile("tcgen05.commit.cta_group::1.mbarrier::arrive::one.shared::cluster.b64 [%0];" :: "r"((uint32_t)(mb)) : "memory")
#define TCGEN05_FENCE_AFTER() asm volatile("tcgen05.fence::after_thread_sync;" ::: "memory")
#define TCGEN05_FENCE_BEFORE() asm volatile("tcgen05.fence::before_thread_sync;" ::: "memory")
#define TCGEN05_WAIT_LD() asm volatile("tcgen05.wait::ld.sync.aligned;" ::: "memory")
#define MBARRIER_INIT(mb, cnt) \
    asm volatile("mbarrier.init.shared.b64 [%0], %1;" :: "r"((uint32_t)(mb)), "r"((uint32_t)(cnt)) : "memory")
#define MBARRIER_INVAL(mb) \
    asm volatile("mbarrier.inval.shared.b64 [%0];" :: "r"((uint32_t)(mb)) : "memory")
#define MBARRIER_EXPECT_TX(mb, tx) \
    asm volatile("mbarrier.arrive.expect_tx.shared.b64 _, [%0], %1;" :: "r"((uint32_t)(mb)), "r"((uint32_t)(tx)) : "memory")
#define MBARRIER_WAIT_PARITY(mb, par) do {                                           \
    uint32_t _mb = (uint32_t)(mb); uint32_t _p = (uint32_t)(par); uint32_t _d;       \
    asm volatile("{\n\t.reg .pred p;\n\t"                                            \
        "mbarrier.try_wait.parity.acquire.cta.shared::cta.b64 p, [%1], %2;\n\t"      \
        "selp.b32 %0, 1, 0, p;\n\t}" : "=r"(_d) : "r"(_mb), "r"(_p) : "memory");     \
    if (!_d) {                                                                       \
        asm volatile("{\n\t.reg .pred P1;\n\t"                                       \
            "WL_%=:\n\t"                                                             \
            "mbarrier.try_wait.parity.acquire.cta.shared::cta.b64 P1, [%0], %1, 0x989680;\n\t" \
            "@P1 bra.uni WD_%=;\n\t"                                                 \
            "bra.uni WL_%=;\n\t"                                                     \
            "WD_%=:\n\t}" :: "r"(_mb), "r"(_p) : "memory");                          \
    }                                                                                \
} while (0)

__device__ __forceinline__ void cp_bulk(uint32_t dst, const void* src, uint32_t bytes, uint32_t mb) {
    asm volatile("cp.async.bulk.shared::cta.global.mbarrier::complete_tx::bytes [%0], [%1], %2, [%3];"
                 :: "r"(dst), "l"(src), "r"(bytes), "r"(mb) : "memory");
}

#define TCGEN05_LD_32X32B_X32(r, ta) \
    asm volatile( \
        "tcgen05.ld.sync.aligned.32x32b.x32.b32 " \
        "{%0, %1, %2, %3, %4, %5, %6, %7, " \
        " %8, %9, %10, %11, %12, %13, %14, %15, " \
        " %16, %17, %18, %19, %20, %21, %22, %23, " \
        " %24, %25, %26, %27, %28, %29, %30, %31}, [%32];" \
        : "=r"((r)[0]),  "=r"((r)[1]),  "=r"((r)[2]),  "=r"((r)[3]), \
          "=r"((r)[4]),  "=r"((r)[5]),  "=r"((r)[6]),  "=r"((r)[7]), \
          "=r"((r)[8]),  "=r"((r)[9]),  "=r"((r)[10]), "=r"((r)[11]), \
          "=r"((r)[12]), "=r"((r)[13]), "=r"((r)[14]), "=r"((r)[15]), \
          "=r"((r)[16]), "=r"((r)[17]), "=r"((r)[18]), "=r"((r)[19]), \
          "=r"((r)[20]), "=r"((r)[21]), "=r"((r)[22]), "=r"((r)[23]), \
          "=r"((r)[24]), "=r"((r)[25]), "=r"((r)[26]), "=r"((r)[27]), \
          "=r"((r)[28]), "=r"((r)[29]), "=r"((r)[30]), "=r"((r)[31]) \
        : "r"(ta))

static constexpr uint64_t SMEM_DESC_BASE_SW128 =
    (uint64_t(2) << 61) | (uint64_t(1) << 46) | (uint64_t(64) << 32) | (uint64_t(1) << 16);
#define MAKE_SMEM_DESC(ba) (SMEM_DESC_BASE_SW128 | ((uint64_t)((ba) >> 4) & 0x3FFF))

// Proven operand binding: %3 = idesc, %4 = enable, %5 = zero reg.
__device__ __forceinline__ void mma_f16_ss(uint32_t d, uint64_t da, uint64_t db,
                                           uint32_t idesc, bool en) {
    uint32_t e = en ? 1u : 0u;
    asm volatile(
        "{\n\t.reg .pred p;\n\t"
        "setp.ne.u32 p, %4, 0;\n\t"
        "tcgen05.mma.cta_group::1.kind::f16 [%0], %1, %2, %3, {%5, %5, %5, %5}, p;\n\t"
        "}"
        :: "r"(d), "l"(da), "l"(db), "r"(idesc), "r"(e), "r"(0u)
        : "memory");
}
// idesc: f32 accum, FP16 a (0), FP16 b (0), N=128, M=128
static constexpr uint32_t MMA_IDESC =
    (1u << 4) | ((128u / 8) << 17) | ((128u / 16) << 24);
#endif // HAS_TCGEN05

#define GK 512
#define NCHUNKS 8
#define TILE_BYTES 16384

// ---------------------------------------------------------------------------
// fp16 GEMM: 128x128 tile, 3-stage pipeline (Round-12/13 proven).
// OUTH: write C as fp16 (QKV intermediates); else fp32 with bias/mask epilogue.
// ---------------------------------------------------------------------------
#define STAGE_BYTES (2 * TILE_BYTES)
#define NSTAGES 3
#define GEMM_DYN_SMEM (NSTAGES * STAGE_BYTES + 1024)

template <bool EPI, bool OUTH>
__global__ void __launch_bounds__(256)
gemm_fp16(const __half* __restrict__ A, const __half* __restrict__ B,
          void* __restrict__ Cv, int ldc,
          const float* __restrict__ bias, const int* __restrict__ post_mask)
{
    extern __shared__ char dyn_smem[];
    const int tid = threadIdx.x;
    const int wid = tid >> 5;
    const int lane = tid & 31;
    const int m0 = blockIdx.y << 7;
    const int n0 = blockIdx.x << 7;
    const int pm = blockIdx.y;
    const int pn = blockIdx.x;

    const uint32_t sbase = (smem_u32(dyn_smem) + 1023u) & ~1023u;

#if HAS_TCGEN05
    __shared__ uint32_t s_tmem_ptr[2];
    __shared__ __align__(8) uint64_t s_full[NSTAGES];
    __shared__ __align__(8) uint64_t s_empty[NSTAGES];
    __shared__ __align__(8) uint64_t s_done;

    if (wid == 0) {
        TCGEN05_ALLOC(smem_u32(s_tmem_ptr), 128);
        TCGEN05_RELINQ();
    }
    if (tid == 0) {
#pragma unroll
        for (int j = 0; j < NSTAGES; ++j) {
            MBARRIER_INIT(smem_u32(&s_full[j]), 1);
            MBARRIER_INIT(smem_u32(&s_empty[j]), 1);
        }
        MBARRIER_INIT(smem_u32(&s_done), 1);
    }
    __syncthreads();

    uint32_t tmem_base;
    asm volatile("ld.shared.b32 %0, [%1];" : "=r"(tmem_base) : "r"(smem_u32(s_tmem_ptr)));

    if (wid == 0 && elect_one_pred()) {
        uint32_t fa[NSTAGES], ea[NSTAGES];
#pragma unroll
        for (int j = 0; j < NSTAGES; ++j) {
            fa[j] = smem_u32(&s_full[j]);
            ea[j] = smem_u32(&s_empty[j]);
        }
        const char* pA = (const char*)A + (size_t)pm * (8 * TILE_BYTES);
        const char* pB = (const char*)B + (size_t)pn * (8 * TILE_BYTES);

        auto load_chunk = [&](int ch, int st) {
            const uint32_t sb = sbase + st * STAGE_BYTES;
            const uint32_t mb = fa[st];
            MBARRIER_EXPECT_TX(mb, STAGE_BYTES);
            const size_t o = (size_t)ch * TILE_BYTES;
            cp_bulk(sb,              pA + o, TILE_BYTES, mb);
            cp_bulk(sb + TILE_BYTES, pB + o, TILE_BYTES, mb);
        };

        load_chunk(0, 0);
        load_chunk(1, 1);
        load_chunk(2, 2);

        int fph[NSTAGES] = {0, 0, 0};
        int eph[NSTAGES] = {0, 0, 0};

        for (int c = 0; c < NCHUNKS; ++c) {
            const int st = c % NSTAGES;
            MBARRIER_WAIT_PARITY(fa[st], fph[st]);
            fph[st] ^= 1;

            const uint32_t sb = sbase + st * STAGE_BYTES;
            const uint64_t dA = MAKE_SMEM_DESC(sb);
            const uint64_t dB = MAKE_SMEM_DESC(sb + TILE_BYTES);
#pragma unroll
            for (int s = 0; s < 4; ++s) {
                const bool first = (c == 0) && (s == 0);
                mma_f16_ss(tmem_base, dA + 2 * s, dB + 2 * s, MMA_IDESC, !first);
            }
            if (c + NSTAGES < NCHUNKS) {
                TCGEN05_COMMIT(ea[st]);
                MBARRIER_WAIT_PARITY(ea[st], eph[st]);
                eph[st] ^= 1;
                load_chunk(c + NSTAGES, st);
            } else if (c == NCHUNKS - 1) {
                TCGEN05_COMMIT(smem_u32(&s_done));
            }
        }
    }

    MBARRIER_WAIT_PARITY(smem_u32(&s_done), 0);
    TCGEN05_FENCE_AFTER();

    {
        const int rsub = (wid & 3) << 5;
        const int colh = (wid >> 2) << 6;
        const int m = m0 + rsub + lane;
        bool zero = false;
        if (EPI) zero = (post_mask[m] != 0);

#pragma unroll
        for (int half = 0; half < 2; ++half) {
            const int cbase = colh + half * 32;
            uint32_t r[32];
            TCGEN05_LD_32X32B_X32(r, tmem_base + cbase);
            TCGEN05_WAIT_LD();
#pragma unroll
            for (int j = 0; j < 32; j += 4) {
                float v[4];
                v[0] = __uint_as_float(r[j + 0]);
                v[1] = __uint_as_float(r[j + 1]);
                v[2] = __uint_as_float(r[j + 2]);
                v[3] = __uint_as_float(r[j + 3]);
                if (EPI) {
                    const int n = n0 + cbase + j;
                    v[0] += bias[n + 0];
                    v[1] += bias[n + 1];
                    v[2] += bias[n + 2];
                    v[3] += bias[n + 3];
                    if (zero) { v[0] = 0.f; v[1] = 0.f; v[2] = 0.f; v[3] = 0.f; }
                }
                if (OUTH) {
                    __half* crow = (__half*)Cv + (size_t)m * ldc + n0;
                    uint2 hv;
                    pack4h(v, hv);
                    *(uint2*)(crow + cbase + j) = hv;
                } else {
                    float* crow = (float*)Cv + (size_t)m * ldc + n0;
                    float4 fv;
                    fv.x = v[0]; fv.y = v[1]; fv.z = v[2]; fv.w = v[3];
                    *(float4*)(crow + cbase + j) = fv;
                }
            }
        }
        TCGEN05_FENCE_BEFORE();
    }

    __syncthreads();
    if (tid == 0) {
#pragma unroll
        for (int j = 0; j < NSTAGES; ++j) {
            MBARRIER_INVAL(smem_u32(&s_full[j]));
            MBARRIER_INVAL(smem_u32(&s_empty[j]));
        }
        MBARRIER_INVAL(smem_u32(&s_done));
    }
    __syncthreads();
    if (wid == 0) TCGEN05_DEALLOC(tmem_base, 128);

#else
    // =========================== mma.sync fallback ==========================
    const int wm = (wid & 1) << 6;
    const int wn = (wid >> 1) << 5;

    auto issue_loads = [&](int ch, int st) {
        const uint32_t sb = sbase + st * STAGE_BYTES;
        const char* pA = (const char*)A + ((size_t)pm * 8 + ch) * TILE_BYTES;
        const char* pB = (const char*)B + ((size_t)pn * 8 + ch) * TILE_BYTES;
#pragma unroll
        for (int i = 0; i < 4; ++i) {
            const uint32_t u = (tid + (i << 8)) << 4;
            cp16(sb + u, pA + u);
            cp16(sb + TILE_BYTES + u, pB + u);
        }
        asm volatile("cp.async.commit_group;" ::: "memory");
    };

    float acc[4][4][4];
#pragma unroll
    for (int a = 0; a < 4; ++a)
#pragma unroll
        for (int b = 0; b < 4; ++b)
#pragma unroll
            for (int d = 0; d < 4; ++d) acc[a][b][d] = 0.f;

    issue_loads(0, 0);
    issue_loads(1, 1);

    for (int c = 0; c < NCHUNKS; ++c) {
        if (c < NCHUNKS - 1) asm volatile("cp.async.wait_group 1;" ::: "memory");
        else                 asm volatile("cp.async.wait_group 0;" ::: "memory");
        __syncthreads();
        const uint32_t sb = sbase + (c & 1) * STAGE_BYTES;

#pragma unroll
        for (int ks = 0; ks < 4; ++ks) {
            uint32_t av[4][4];
#pragma unroll
            for (int mf = 0; mf < 4; ++mf) {
                const uint32_t row = wm + (mf << 4) + (lane & 15);
                const uint32_t kp = (ks << 1) + (lane >> 4);
                const uint32_t off = (row << 7) + (kp << 4);
                const uint32_t sw = off ^ ((off >> 3) & 0x70);
                ldsm4(av[mf], sb + sw);
            }
            uint32_t bv[4][2];
#pragma unroll
            for (int nb = 0; nb < 2; ++nb) {
                const uint32_t row = wn + (nb << 4) + ((lane >> 4) << 3) + (lane & 7);
                const uint32_t kp = (ks << 1) + ((lane >> 3) & 1);
                const uint32_t off = (row << 7) + (kp << 4);
                const uint32_t sw = off ^ ((off >> 3) & 0x70);
                uint32_t t[4];
                ldsm4(t, sb + TILE_BYTES + sw);
                bv[2 * nb][0] = t[0]; bv[2 * nb][1] = t[1];
                bv[2 * nb + 1][0] = t[2]; bv[2 * nb + 1][1] = t[3];
            }
#pragma unroll
            for (int mf = 0; mf < 4; ++mf)
#pragma unroll
                for (int nf = 0; nf < 4; ++nf)
                    mma_fp16(acc[mf][nf], av[mf], bv[nf]);
        }
        __syncthreads();
        if (c + 2 < NCHUNKS) issue_loads(c + 2, (c + 2) & 1);
    }

#pragma unroll
    for (int mf = 0; mf < 4; ++mf) {
#pragma unroll
        for (int half = 0; half < 2; ++half) {
            const int m = m0 + wm + (mf << 4) + (half << 3) + (lane >> 2);
            bool zero = false;
            if (EPI) zero = (post_mask[m] != 0);
#pragma unroll
            for (int nf = 0; nf < 4; ++nf) {
                const int col = n0 + wn + (nf << 3) + ((lane & 3) << 1);
                float v0 = acc[mf][nf][half * 2 + 0];
                float v1 = acc[mf][nf][half * 2 + 1];
                if (EPI) {
                    v0 += bias[col];
                    v1 += bias[col + 1];
                    if (zero) { v0 = 0.f; v1 = 0.f; }
                }
                if (OUTH) {
                    __half* crow = (__half*)Cv + (size_t)m * ldc;
                    __half2 h2;
                    h2.x = __float2half(v0);
                    h2.y = __float2half(v1);
                    *(__half2*)(crow + col) = h2;
                } else {
                    float* crow = (float*)Cv + (size_t)m * ldc;
                    crow[col] = v0;
                    crow[col + 1] = v1;
                }
            }
        }
    }
#endif
}

// ---------------------------------------------------------------------------
// Splits: fp32 -> fp16 into TILED+SWIZZLED layout.
// ---------------------------------------------------------------------------
__global__ void __launch_bounds__(256)
split_tiledA(const float* __restrict__ in, __half* __restrict__ hh,
             __half* __restrict__ qh, int Mtot, int withQ)
{
    int i = blockIdx.x * blockDim.x + threadIdx.x;
    const int units = Mtot << 6;
    if (i >= units) return;
    const int m = i >> 6;
    const int k = (i & 63) << 3;

    float x[8];
    const float* src = in + (size_t)m * GK + k;
#pragma unroll
    for (int j = 0; j < 8; ++j) x[j] = src[j];

    uint4 hv;
    pack8h(x, hv);

    const size_t o = tiled_off(m, k);
    *(uint4*)((char*)hh + o) = hv;

    if (withQ && (m & 255) < 64) {
        const int mq = ((m >> 8) << 6) + (m & 63);
        const size_t oq = tiled_off(mq, k);
        *(uint4*)((char*)qh + oq) = hv;
    }
}

__global__ void __launch_bounds__(256)
splitT_tiled(const float* __restrict__ in, __half* __restrict__ hT, int Nd)
{
    int i = blockIdx.x * blockDim.x + threadIdx.x;
    const int units = Nd << 6;
    if (i >= units) return;
    const int n = i >> 6;
    const int k = (i & 63) << 3;

    float x[8];
#pragma unroll
    for (int j = 0; j < 8; ++j) x[j] = in[(size_t)(k + j) * Nd + n];
    uint4 hv;
    pack8h(x, hv);

    const size_t o = tiled_off(n, k);
    *(uint4*)((char*)hT + o) = hv;
}

// ---------------------------------------------------------------------------
// Attention v4: HMMA (mma.sync m16n8k16) for S and P@V; proven bitmask softmax.
// One CTA per (head, batch), 256 threads = 8 warps, 1 CTA/SM (184KB smem).
//
// smem (bytes):
//   sQ   fp16 [64][72]    @ 0        (9216)   - Q, pre-scaled by 1/8
//   sK   fp16 [256][72]   @ 9216     (36864)
//   sV   fp16 [256][72]   @ 46080    (36864)
//   sS   fp32 [64][260]   @ 82944    (66560)
//   sP   fp16 [64][264]   @ 149504   (33792)  - unnormalized exp weights
//   sRed fp32 [256]       @ 183296
//   sInv fp32 [64]        @ 184320
// ---------------------------------------------------------------------------
#define AT_QS 72
#define AT_KS 72
#define AT_SS 260
#define AT_PS 264
#define ATTN_SMEM_BYTES 184576

__global__ void __launch_bounds__(256)
attn_kernel(const __half* __restrict__ Q,
            const __half* __restrict__ KV,
            const int* __restrict__ pre_mask,
            __half* __restrict__ Ah)
{
    extern __shared__ char smem[];
    __half* sQ  = (__half*)(smem);
    __half* sK  = (__half*)(smem + 9216);
    __half* sV  = (__half*)(smem + 46080);
    float*  sS  = (float*)(smem + 82944);
    __half* sP  = (__half*)(smem + 149504);
    float*  sRed = (float*)(smem + 183296);
    float*  sInv = (float*)(smem + 184320);

    const int tid = threadIdx.x;
    const int wid = tid >> 5;
    const int lane = tid & 31;
    const int h = blockIdx.x;
    const int bs = blockIdx.y;
    const float NEG_INF = -INFINITY;

    // ---- load Q (scaled 1/8), K, V into padded fp16 smem ----
    {
        const __half2 hsc = __half2half2(__float2half(0.125f));
#pragma unroll
        for (int it = 0; it < 2; ++it) {
            const int u = tid + (it << 8);       // 0..511
            const int q = u >> 3, c = u & 7;
            uint4 v = *(const uint4*)(Q + ((size_t)(bs * NQ + q) << 9) + h * HEAD_DIM + (c << 3));
            __half2* hp = (__half2*)&v;
#pragma unroll
            for (int j = 0; j < 4; ++j) hp[j] = __hmul2(hp[j], hsc);
            *(uint4*)(sQ + q * AT_QS + (c << 3)) = v;
        }
#pragma unroll
        for (int it = 0; it < 8; ++it) {
            const int u = tid + (it << 8);       // 0..2047
            const int e = u >> 3, c = u & 7;
            const size_t base = ((size_t)(bs * NE + e) << 10) + h * HEAD_DIM + (c << 3);
            *(uint4*)(sK + e * AT_KS + (c << 3)) = *(const uint4*)(KV + base);
            *(uint4*)(sV + e * AT_KS + (c << 3)) = *(const uint4*)(KV + base + EMBED_DIM);
        }
    }
    __syncthreads();

    // ---- S = Qs @ K^T via mma: warp w -> entity cols [32w, 32w+32), all 64 q ----
    {
        const int n0w = wid << 5;
        float acc[4][4][4];
#pragma unroll
        for (int i = 0; i < 4; ++i)
#pragma unroll
            for (int j = 0; j < 4; ++j)
#pragma unroll
                for (int d = 0; d < 4; ++d) acc[i][j][d] = 0.f;

#pragma unroll
        for (int ks = 0; ks < 4; ++ks) {
            uint32_t a[4][4];
#pragma unroll
            for (int i = 0; i < 4; ++i) {
                const int row = (i << 4) + (lane & 15);
                const int col = (ks << 4) + ((lane >> 4) << 3);
                ldsm4(a[i], smem_u32(sQ + row * AT_QS + col));
            }
            uint32_t b[4][2];
#pragma unroll
            for (int nb = 0; nb < 2; ++nb) {
                const int row = n0w + (nb << 4) + ((lane >> 4) << 3) + (lane & 7);
                const int col = (ks << 4) + (((lane >> 3) & 1) << 3);
                uint32_t t[4];
                ldsm4(t, smem_u32(sK + row * AT_KS + col));
                b[2 * nb][0] = t[0]; b[2 * nb][1] = t[1];
                b[2 * nb + 1][0] = t[2]; b[2 * nb + 1][1] = t[3];
            }
#pragma unroll
            for (int i = 0; i < 4; ++i)
#pragma unroll
                for (int j = 0; j < 4; ++j)
                    mma_fp16(acc[i][j], a[i], b[j]);
        }
        // store S fragments: lane g = lane>>2 (rows), t2 = (lane&3)*2 (cols)
        const int g = lane >> 2;
        const int t2 = (lane & 3) << 1;
#pragma unroll
        for (int i = 0; i < 4; ++i) {
#pragma unroll
            for (int j = 0; j < 4; ++j) {
                const int q = (i << 4) + g;
                const int k = n0w + (j << 3) + t2;
                float2 lo; lo.x = acc[i][j][0]; lo.y = acc[i][j][1];
                float2 hi; hi.x = acc[i][j][2]; hi.y = acc[i][j][3];
                *(float2*)&sS[q * AT_SS + k] = lo;
                *(float2*)&sS[(q + 8) * AT_SS + k] = hi;
            }
        }
    }
    __syncthreads();

    // ---- masked softmax (bitmask; interleaved float4 parts) ----
    {
        const int row = tid >> 2;
        const int part = tid & 3;

        const int4* mrow = (const int4*)(pre_mask + ((size_t)bs * NQ + row) * NE);
        uint64_t bits = 0;
#pragma unroll
        for (int it = 0; it < 16; ++it) {
            int4 m = mrow[(it << 2) + part];   // k = it*16 + part*4
            uint64_t b = (uint64_t)(m.x != 0) | ((uint64_t)(m.y != 0) << 1) |
                         ((uint64_t)(m.z != 0) << 2) | ((uint64_t)(m.w != 0) << 3);
            bits |= b << (it << 2);
        }

        float mx = NEG_INF;
#pragma unroll
        for (int it = 0; it < 16; ++it) {
            float4 v = *(const float4*)&sS[row * AT_SS + (it << 4) + (part << 2)];
            const uint32_t mb = (uint32_t)(bits >> (it << 2)) & 15u;
            if (!(mb & 1u)) mx = fmaxf(mx, v.x);
            if (!(mb & 2u)) mx = fmaxf(mx, v.y);
            if (!(mb & 4u)) mx = fmaxf(mx, v.z);
            if (!(mb & 8u)) mx = fmaxf(mx, v.w);
        }
        sRed[(row << 2) + part] = mx;
        __syncthreads();
        const float rm = fmaxf(fmaxf(sRed[row << 2], sRed[(row << 2) + 1]),
                               fmaxf(sRed[(row << 2) + 2], sRed[(row << 2) + 3]));
        __syncthreads();

        const bool live = (rm != NEG_INF);
        float ssum = 0.f;
#pragma unroll
        for (int it = 0; it < 16; ++it) {
            float4 v = *(const float4*)&sS[row * AT_SS + (it << 4) + (part << 2)];
            const uint32_t mb = (uint32_t)(bits >> (it << 2)) & 15u;
            float e0 = (live && !(mb & 1u)) ? __expf(v.x - rm) : 0.f;
            float e1 = (live && !(mb & 2u)) ? __expf(v.y - rm) : 0.f;
            float e2 = (live && !(mb & 4u)) ? __expf(v.z - rm) : 0.f;
            float e3 = (live && !(mb & 8u)) ? __expf(v.w - rm) : 0.f;
            ssum += (e0 + e1) + (e2 + e3);
            float ev[4] = {e0, e1, e2, e3};
            uint2 hv;
            pack4h(ev, hv);
            *(uint2*)(sP + row * AT_PS + (it << 4) + (part << 2)) = hv;
        }
        sRed[(row << 2) + part] = ssum;
        __syncthreads();
        if (tid < 64) {
            const float t = sRed[tid << 2] + sRed[(tid << 2) + 1] +
                            sRed[(tid << 2) + 2] + sRed[(tid << 2) + 3];
            sInv[tid] = (t > 0.f) ? (1.f / t) : 0.f;
        }
    }
    __syncthreads();

    // ---- out = P @ V via mma: warp w -> q rows [16*(w&3)), d cols [32*(w>>2)) ----
    {
        const int q0 = (wid & 3) << 4;
        const int d0 = (wid >> 2) << 5;
        float acc[4][4];
#pragma unroll
        for (int j = 0; j < 4; ++j)
#pragma unroll
            for (int d = 0; d < 4; ++d) acc[j][d] = 0.f;

#pragma unroll 4
        for (int ks = 0; ks < 16; ++ks) {
            const int e0 = ks << 4;
            uint32_t a[4];
            {
                const int row = q0 + (lane & 15);
                const int col = e0 + ((lane >> 4) << 3);
                ldsm4(a, smem_u32(sP + row * AT_PS + col));
            }
            uint32_t b[4][2];
#pragma unroll
            for (int nb = 0; nb < 2; ++nb) {
                const int row = e0 + (lane & 7) + (((lane >> 3) & 1) << 3);
                const int col = d0 + (nb << 4) + ((lane >> 4) << 3);
                uint32_t t[4];
                ldsm4t(t, smem_u32(sV + row * AT_KS + col));
                b[2 * nb][0] = t[0]; b[2 * nb][1] = t[1];
                b[2 * nb + 1][0] = t[2]; b[2 * nb + 1][1] = t[3];
            }
#pragma unroll
            for (int j = 0; j < 4; ++j)
                mma_fp16(acc[j], a, b[j]);
        }

        // epilogue: scale by 1/sum, pack half2, store to tiled layout
        const int g = lane >> 2;
        const int t2 = (lane & 3) << 1;
        const float inv0 = sInv[q0 + g];
        const float inv1 = sInv[q0 + g + 8];
        const int m0r = bs * NQ + q0 + g;
#pragma unroll
        for (int j = 0; j < 4; ++j) {
            const int d = d0 + (j << 3) + t2;
            const int kk0 = (h * HEAD_DIM + d) & ~7;
            const int sub = ((h * HEAD_DIM + d) & 7) << 1;
            {
                __half2 h2;
                h2.x = __float2half(acc[j][0] * inv0);
                h2.y = __float2half(acc[j][1] * inv0);
                *(uint32_t*)((char*)Ah + tiled_off(m0r, kk0) + sub) = *(uint32_t*)&h2;
            }
            {
                __half2 h2;
                h2.x = __float2half(acc[j][2] * inv1);
                h2.y = __float2half(acc[j][3] * inv1);
                *(uint32_t*)((char*)Ah + tiled_off(m0r + 8, kk0) + sub) = *(uint32_t*)&h2;
            }
        }
    }
}

// ---------------------------------------------------------------------------
// kernel_launch
// ---------------------------------------------------------------------------
extern "C" void kernel_launch(void* const* d_in, const int* in_sizes, int n_in,
                              void* d_out, int out_size)
{
    const float* entities  = (const float*)d_in[0];
    const int*   pre_mask  = (const int*)d_in[1];
    const int*   post_mask = (const int*)d_in[2];
    const float* W_in      = (const float*)d_in[3];
    const float* W_out     = (const float*)d_in[4];
    const float* b_out     = (const float*)d_in[5];
    float* out = (float*)d_out;

    __half *Qs, *KVs;
    __half *eh, *qh, *ah, *wih, *woh;
    cudaGetSymbolAddress((void**)&Qs, g_Q);
    cudaGetSymbolAddress((void**)&KVs, g_KV);
    cudaGetSymbolAddress((void**)&eh, g_ent_h);
    cudaGetSymbolAddress((void**)&qh, g_q_h);
    cudaGetSymbolAddress((void**)&ah, g_attn_h);
    cudaGetSymbolAddress((void**)&wih, g_WinT_h);
    cudaGetSymbolAddress((void**)&woh, g_WoutT_h);

    cudaFuncSetAttribute((const void*)gemm_fp16<false, true>,
                         cudaFuncAttributeMaxDynamicSharedMemorySize, GEMM_DYN_SMEM);
    cudaFuncSetAttribute((const void*)gemm_fp16<true, false>,
                         cudaFuncAttributeMaxDynamicSharedMemorySize, GEMM_DYN_SMEM);
    cudaFuncSetAttribute(attn_kernel,
                         cudaFuncAttributeMaxDynamicSharedMemorySize, ATTN_SMEM_BYTES);

    // 1) split entities -> tiled fp16 (+ compact Q rows)
    {
        int units = (BS * NE) << 6;
        split_tiledA<<<(units + 255) / 256, 256>>>(entities, eh, qh, BS * NE, 1);
    }
    // 2) split+transpose weights -> tiled fp16
    {
        int u1 = QKV_DIM << 6;
        splitT_tiled<<<(u1 + 255) / 256, 256>>>(W_in, wih, QKV_DIM);
        int u2 = OUT_DIM << 6;
        splitT_tiled<<<(u2 + 255) / 256, 256>>>(W_out, woh, OUT_DIM);
    }
    // 3) Q = q_ent @ W_in[:, 0:512]     M=32768, N=512  (fp16 output)
    gemm_fp16<false, true><<<dim3(EMBED_DIM / 128, (BS * NQ) / 128), 256, GEMM_DYN_SMEM>>>(
        qh, wih, Qs, EMBED_DIM, nullptr, nullptr);

    // 4) KV = entities @ W_in[:, 512:1536]  (fp16 output)
    gemm_fp16<false, true><<<dim3((2 * EMBED_DIM) / 128, (BS * NE) / 128), 256, GEMM_DYN_SMEM>>>(
        eh, wih + 262144, KVs, 2 * EMBED_DIM, nullptr, nullptr);

    // 5) attention (HMMA; fp16 in, writes tiled fp16 directly)
    attn_kernel<<<dim3(N_HEADS, BS), 256, ATTN_SMEM_BYTES>>>(Qs, KVs, pre_mask, ah);

    // 6) out = ATTN @ W_out + b_out, post-masked  (fp32 output)
    gemm_fp16<true, false><<<dim3(OUT_DIM / 128, (BS * NQ) / 128), 256, GEMM_DYN_SMEM>>>(
        ah, woh, out, OUT_DIM, b_out, post_mask);
}